// round 8
// baseline (speedup 1.0000x reference)
#include <cuda_runtime.h>

// Problem constants
#define BATCH 128
#define CIN   17
#define TIN   4096
#define C1    32
#define T1    2048   // after pool1
#define C2    64
#define NN    1024   // nodes after pool2
#define DG    16     // GAT out dim

// ---- scratch (static device allocations; no cudaMalloc anywhere) ----
__device__ float g_h1[BATCH * C1 * T1];     // 33.5 MB
__device__ float g_h2[BATCH * C2 * NN];     // 33.5 MB
__device__ float g_hw[BATCH * NN * DG];     // 8.4 MB
__device__ float g_ssrc[BATCH * NN];
__device__ float g_sdst[BATCH * NN];
__device__ float g_smax[BATCH];
__device__ float g_pool[BATCH * DG];

// ============================================================
// conv1: x[b][17][4096] -> relu -> maxpool2 -> g_h1[b][32][2048]
// block: (b, tchunk). 128 threads = 8 oc-groups(x4) * 16 pos-groups(x4 pooled)
// ============================================================
__global__ __launch_bounds__(128) void k_conv1(const float* __restrict__ x,
                                               const float* __restrict__ w,
                                               const float* __restrict__ bias) {
    __shared__ float sin[CIN][132];          // 132 = 128 conv pos + 4 halo
    __shared__ float sw[C1 * CIN * 5];       // 2720 floats
    const int b  = blockIdx.y;
    const int t0 = blockIdx.x * 128;         // conv-position base
    const int tid = threadIdx.x;

    for (int i = tid; i < C1 * CIN * 5; i += 128) sw[i] = w[i];
    for (int i = tid; i < CIN * 132; i += 128) {
        int c = i / 132, p = i - c * 132;
        int t = t0 - 2 + p;
        sin[c][p] = (t >= 0 && t < TIN) ? x[(b * CIN + c) * TIN + t] : 0.f;
    }
    __syncthreads();

    const int ocg = tid & 7, pg = tid >> 3;
    const int oc0 = ocg * 4;
    const int cp0 = pg * 8;                  // 8 conv positions -> 4 pooled

    float acc[4][8];
#pragma unroll
    for (int a = 0; a < 4; a++) {
        float bv = bias[oc0 + a];
#pragma unroll
        for (int p = 0; p < 8; p++) acc[a][p] = bv;
    }

    for (int c = 0; c < CIN; c++) {
        float in[12];
#pragma unroll
        for (int r = 0; r < 12; r++) in[r] = sin[c][cp0 + r];
#pragma unroll
        for (int k = 0; k < 5; k++) {
            float wv[4];
#pragma unroll
            for (int a = 0; a < 4; a++) wv[a] = sw[(oc0 + a) * 85 + c * 5 + k];
#pragma unroll
            for (int a = 0; a < 4; a++)
#pragma unroll
                for (int p = 0; p < 8; p++)
                    acc[a][p] += in[p + k] * wv[a];
        }
    }

    const int pbase = blockIdx.x * 64 + pg * 4;
#pragma unroll
    for (int a = 0; a < 4; a++)
#pragma unroll
        for (int q = 0; q < 4; q++) {
            float v = fmaxf(acc[a][2 * q], acc[a][2 * q + 1]);
            v = fmaxf(v, 0.f);
            g_h1[(b * C1 + oc0 + a) * T1 + pbase + q] = v;
        }
}

// ============================================================
// conv2: g_h1[b][32][2048] -> relu -> maxpool2 -> g_h2[b][64][1024]
// block: (tchunk, b, oc-half). weights stored transposed in smem
// (sw[(c*5+k)*32 + oc]) to dodge the stride-640 (mod 32 == 0) bank conflict.
// ============================================================
__global__ __launch_bounds__(128) void k_conv2(const float* __restrict__ w,
                                               const float* __restrict__ bias) {
    __shared__ float sin[C1][132];           // 16.9 KB
    __shared__ float sw[32 * C1 * 5];        // 20.5 KB (half the ocs)
    const int b      = blockIdx.y;
    const int ocbase = blockIdx.z * 32;
    const int t0     = blockIdx.x * 128;
    const int tid    = threadIdx.x;

    // transposed weight load: smem writes coalesced (oc fastest)
    for (int i = tid; i < 32 * C1 * 5; i += 128) {
        int oc = i & 31, r = i >> 5;         // r in [0,160)
        sw[r * 32 + oc] = w[(ocbase + oc) * (C1 * 5) + r];
    }
    for (int i = tid; i < C1 * 132; i += 128) {
        int c = i / 132, p = i - c * 132;
        int t = t0 - 2 + p;
        sin[c][p] = (t >= 0 && t < T1) ? g_h1[(b * C1 + c) * T1 + t] : 0.f;
    }
    __syncthreads();

    const int ocg = tid & 7, pg = tid >> 3;
    const int oc0 = ocg * 4;
    const int cp0 = pg * 8;

    float acc[4][8];
#pragma unroll
    for (int a = 0; a < 4; a++) {
        float bv = bias[ocbase + oc0 + a];
#pragma unroll
        for (int p = 0; p < 8; p++) acc[a][p] = bv;
    }

    for (int c = 0; c < C1; c++) {
        float in[12];
#pragma unroll
        for (int r = 0; r < 12; r++) in[r] = sin[c][cp0 + r];
#pragma unroll
        for (int k = 0; k < 5; k++) {
            float wv[4];
#pragma unroll
            for (int a = 0; a < 4; a++) wv[a] = sw[(c * 5 + k) * 32 + oc0 + a];
#pragma unroll
            for (int a = 0; a < 4; a++)
#pragma unroll
                for (int p = 0; p < 8; p++)
                    acc[a][p] += in[p + k] * wv[a];
        }
    }

    const int pbase = blockIdx.x * 64 + pg * 4;
#pragma unroll
    for (int a = 0; a < 4; a++)
#pragma unroll
        for (int q = 0; q < 4; q++) {
            float v = fmaxf(acc[a][2 * q], acc[a][2 * q + 1]);
            v = fmaxf(v, 0.f);
            g_h2[(b * C2 + ocbase + oc0 + a) * NN + pbase + q] = v;
        }
}

// ============================================================
// hw[b][n][16] = sum_d h2[b][d][n] * gat_w[o][d];  s_src/s_dst scalars
// one thread per (b, n); gat_w transposed to smem for float4 broadcast reads
// ============================================================
__global__ __launch_bounds__(256) void k_hw(const float* __restrict__ gw,
                                            const float* __restrict__ asrc,
                                            const float* __restrict__ adst) {
    __shared__ float4 swt4[64 * 4];          // wT[d][o] as float4 rows
    float* swt = (float*)swt4;
    const int b = blockIdx.y;
    const int n = blockIdx.x * 256 + threadIdx.x;

    for (int i = threadIdx.x; i < 1024; i += 256) {
        int o = i >> 6, d = i & 63;
        swt[d * 16 + o] = gw[i];
    }
    __syncthreads();

    float acc[16];
#pragma unroll
    for (int o = 0; o < 16; o++) acc[o] = 0.f;

    const float* h2p = &g_h2[(size_t)b * C2 * NN + n];
    for (int d = 0; d < 64; d++) {
        float v = h2p[(size_t)d * NN];
        float4 w0 = swt4[d * 4 + 0], w1 = swt4[d * 4 + 1];
        float4 w2 = swt4[d * 4 + 2], w3 = swt4[d * 4 + 3];
        acc[0]  += v * w0.x; acc[1]  += v * w0.y; acc[2]  += v * w0.z; acc[3]  += v * w0.w;
        acc[4]  += v * w1.x; acc[5]  += v * w1.y; acc[6]  += v * w1.z; acc[7]  += v * w1.w;
        acc[8]  += v * w2.x; acc[9]  += v * w2.y; acc[10] += v * w2.z; acc[11] += v * w2.w;
        acc[12] += v * w3.x; acc[13] += v * w3.y; acc[14] += v * w3.z; acc[15] += v * w3.w;
    }

    float ss = 0.f, sd = 0.f;
#pragma unroll
    for (int o = 0; o < 16; o++) {
        ss += acc[o] * __ldg(&asrc[o]);
        sd += acc[o] * __ldg(&adst[o]);
    }

    float4* outp = (float4*)&g_hw[(size_t)(b * NN + n) * 16];
    outp[0] = make_float4(acc[0], acc[1], acc[2], acc[3]);
    outp[1] = make_float4(acc[4], acc[5], acc[6], acc[7]);
    outp[2] = make_float4(acc[8], acc[9], acc[10], acc[11]);
    outp[3] = make_float4(acc[12], acc[13], acc[14], acc[15]);
    g_ssrc[b * NN + n] = ss;
    g_sdst[b * NN + n] = sd;
}

// ============================================================
// per-batch max of s_src (row-max via monotone lrelu factorization),
// also zero-inits the pooled accumulator
// ============================================================
__global__ __launch_bounds__(256) void k_smax() {
    __shared__ float sm[256];
    const int b = blockIdx.x;
    float m = -1e30f;
    for (int i = threadIdx.x; i < NN; i += 256) m = fmaxf(m, g_ssrc[b * NN + i]);
    sm[threadIdx.x] = m;
    __syncthreads();
    for (int s = 128; s > 0; s >>= 1) {
        if (threadIdx.x < s) sm[threadIdx.x] = fmaxf(sm[threadIdx.x], sm[threadIdx.x + s]);
        __syncthreads();
    }
    if (threadIdx.x == 0) g_smax[b] = sm[0];
    if (threadIdx.x < DG) g_pool[b * DG + threadIdx.x] = 0.f;
}

// ============================================================
// dense GAT: for each i, sum over all j of w_ij * hw_j (+ duplicated
// self-loop), then out = num/den + gat_b, block-reduced into g_pool.
// All inner-loop LDS are warp-broadcast (same j across lanes).
// ============================================================
__global__ __launch_bounds__(256) void k_gat(const float* __restrict__ gat_b) {
    __shared__ float  ss[256];
    __shared__ float4 shw[256 * 4];          // 16 KB
    __shared__ float  ps[DG];
    const int b = blockIdx.y;
    const int i = blockIdx.x * 256 + threadIdx.x;

    if (threadIdx.x < DG) ps[threadIdx.x] = 0.f;

    const float sd  = g_sdst[b * NN + i];
    const float ssi = g_ssrc[b * NN + i];
    float m = sd + g_smax[b];
    m = (m >= 0.f) ? m : 0.2f * m;

    float num[16];
#pragma unroll
    for (int o = 0; o < 16; o++) num[o] = 0.f;
    float den = 0.f;

    for (int jt = 0; jt < 4; jt++) {
        __syncthreads();
        ss[threadIdx.x] = g_ssrc[b * NN + jt * 256 + threadIdx.x];
        const float4* src = (const float4*)&g_hw[(size_t)(b * NN + jt * 256) * 16];
        for (int r = threadIdx.x; r < 1024; r += 256) shw[r] = src[r];
        __syncthreads();

#pragma unroll 4
        for (int j = 0; j < 256; j++) {
            float e = sd + ss[j];
            e = (e >= 0.f) ? e : 0.2f * e;
            float wv = __expf(e - m);
            den += wv;
            float4 h0 = shw[j * 4 + 0], h1 = shw[j * 4 + 1];
            float4 h2 = shw[j * 4 + 2], h3 = shw[j * 4 + 3];
            num[0]  += wv * h0.x; num[1]  += wv * h0.y; num[2]  += wv * h0.z; num[3]  += wv * h0.w;
            num[4]  += wv * h1.x; num[5]  += wv * h1.y; num[6]  += wv * h1.z; num[7]  += wv * h1.w;
            num[8]  += wv * h2.x; num[9]  += wv * h2.y; num[10] += wv * h2.z; num[11] += wv * h2.w;
            num[12] += wv * h3.x; num[13] += wv * h3.y; num[14] += wv * h3.z; num[15] += wv * h3.w;
        }
    }

    // PyG add_self_loops duplicates the (i,i) edge: add it once more
    {
        float e = sd + ssi;
        e = (e >= 0.f) ? e : 0.2f * e;
        float wv = __expf(e - m);
        den += wv;
        const float4* hp = (const float4*)&g_hw[(size_t)(b * NN + i) * 16];
        float4 h0 = __ldg(&hp[0]), h1 = __ldg(&hp[1]);
        float4 h2 = __ldg(&hp[2]), h3 = __ldg(&hp[3]);
        num[0]  += wv * h0.x; num[1]  += wv * h0.y; num[2]  += wv * h0.z; num[3]  += wv * h0.w;
        num[4]  += wv * h1.x; num[5]  += wv * h1.y; num[6]  += wv * h1.z; num[7]  += wv * h1.w;
        num[8]  += wv * h2.x; num[9]  += wv * h2.y; num[10] += wv * h2.z; num[11] += wv * h2.w;
        num[12] += wv * h3.x; num[13] += wv * h3.y; num[14] += wv * h3.z; num[15] += wv * h3.w;
    }

    const float inv = 1.f / den;
#pragma unroll
    for (int o = 0; o < 16; o++) {
        float v = num[o] * inv + __ldg(&gat_b[o]);
        atomicAdd(&ps[o], v);
    }
    __syncthreads();
    if (threadIdx.x < DG) atomicAdd(&g_pool[b * DG + threadIdx.x], ps[threadIdx.x]);
}

// ============================================================
// final: mean over nodes + fc -> out[b][2]
// ============================================================
__global__ __launch_bounds__(128) void k_fc(const float* __restrict__ fcw,
                                            const float* __restrict__ fcb,
                                            float* __restrict__ out) {
    const int b = threadIdx.x;
    if (b < BATCH) {
        float r0 = __ldg(&fcb[0]), r1 = __ldg(&fcb[1]);
#pragma unroll
        for (int o = 0; o < 16; o++) {
            float p = g_pool[b * DG + o] * (1.0f / (float)NN);
            r0 += p * __ldg(&fcw[o]);
            r1 += p * __ldg(&fcw[16 + o]);
        }
        out[b * 2 + 0] = r0;
        out[b * 2 + 1] = r1;
    }
}

extern "C" void kernel_launch(void* const* d_in, const int* in_sizes, int n_in,
                              void* d_out, int out_size) {
    const float* x    = (const float*)d_in[0];
    const float* c1w  = (const float*)d_in[1];
    const float* c1b  = (const float*)d_in[2];
    const float* c2w  = (const float*)d_in[3];
    const float* c2b  = (const float*)d_in[4];
    const float* gw   = (const float*)d_in[5];
    const float* asrc = (const float*)d_in[6];
    const float* adst = (const float*)d_in[7];
    const float* gb   = (const float*)d_in[8];
    const float* fcw  = (const float*)d_in[9];
    const float* fcb  = (const float*)d_in[10];
    float* out = (float*)d_out;

    k_conv1<<<dim3(32, BATCH), 128>>>(x, c1w, c1b);
    k_conv2<<<dim3(16, BATCH, 2), 128>>>(c2w, c2b);
    k_hw<<<dim3(4, BATCH), 256>>>(gw, asrc, adst);
    k_smax<<<BATCH, 256>>>();
    k_gat<<<dim3(4, BATCH), 256>>>(gb);
    k_fc<<<1, 128>>>(fcw, fcb, out);
}

// round 9
// speedup vs baseline: 1.5964x; 1.5964x over previous
#include <cuda_runtime.h>

// Problem constants
#define BATCH 128
#define CIN   17
#define TIN   4096
#define C1    32
#define T1    2048   // after pool1
#define C2    64
#define NN    1024   // nodes after pool2
#define DG    16     // GAT out dim

// ---- scratch (static device allocations; no cudaMalloc anywhere) ----
__device__ float g_h1[BATCH * C1 * T1];     // 33.5 MB
__device__ float g_h2[BATCH * C2 * NN];     // 33.5 MB
__device__ float g_hw[BATCH * NN * DG];     // 8.4 MB
__device__ float g_ssrc[BATCH * NN];
__device__ float g_sdst[BATCH * NN];

// ============================================================
// conv1: x[b][17][4096] -> relu -> maxpool2 -> g_h1[b][32][2048]
// ============================================================
__global__ __launch_bounds__(128) void k_conv1(const float* __restrict__ x,
                                               const float* __restrict__ w,
                                               const float* __restrict__ bias) {
    __shared__ float sin[CIN][132];          // 132 = 128 conv pos + 4 halo
    __shared__ float sw[C1 * CIN * 5];       // 2720 floats
    const int b  = blockIdx.y;
    const int t0 = blockIdx.x * 128;         // conv-position base
    const int tid = threadIdx.x;

    for (int i = tid; i < C1 * CIN * 5; i += 128) sw[i] = w[i];
    for (int i = tid; i < CIN * 132; i += 128) {
        int c = i / 132, p = i - c * 132;
        int t = t0 - 2 + p;
        sin[c][p] = (t >= 0 && t < TIN) ? x[(b * CIN + c) * TIN + t] : 0.f;
    }
    __syncthreads();

    const int ocg = tid & 7, pg = tid >> 3;
    const int oc0 = ocg * 4;
    const int cp0 = pg * 8;                  // 8 conv positions -> 4 pooled

    float acc[4][8];
#pragma unroll
    for (int a = 0; a < 4; a++) {
        float bv = bias[oc0 + a];
#pragma unroll
        for (int p = 0; p < 8; p++) acc[a][p] = bv;
    }

    for (int c = 0; c < CIN; c++) {
        float in[12];
#pragma unroll
        for (int r = 0; r < 12; r++) in[r] = sin[c][cp0 + r];
#pragma unroll
        for (int k = 0; k < 5; k++) {
            float wv[4];
#pragma unroll
            for (int a = 0; a < 4; a++) wv[a] = sw[(oc0 + a) * 85 + c * 5 + k];
#pragma unroll
            for (int a = 0; a < 4; a++)
#pragma unroll
                for (int p = 0; p < 8; p++)
                    acc[a][p] += in[p + k] * wv[a];
        }
    }

    const int pbase = blockIdx.x * 64 + pg * 4;
#pragma unroll
    for (int a = 0; a < 4; a++)
#pragma unroll
        for (int q = 0; q < 4; q++) {
            float v = fmaxf(acc[a][2 * q], acc[a][2 * q + 1]);
            v = fmaxf(v, 0.f);
            g_h1[(b * C1 + oc0 + a) * T1 + pbase + q] = v;
        }
}

// ============================================================
// conv2: g_h1[b][32][2048] -> relu -> maxpool2 -> g_h2[b][64][1024]
// ============================================================
__global__ __launch_bounds__(128) void k_conv2(const float* __restrict__ w,
                                               const float* __restrict__ bias) {
    __shared__ float sin[C1][132];           // 16.9 KB
    __shared__ float sw[32 * C1 * 5];        // 20.5 KB (half the ocs)
    const int b      = blockIdx.y;
    const int ocbase = blockIdx.z * 32;
    const int t0     = blockIdx.x * 128;
    const int tid    = threadIdx.x;

    // transposed weight load: smem writes coalesced (oc fastest)
    for (int i = tid; i < 32 * C1 * 5; i += 128) {
        int oc = i & 31, r = i >> 5;         // r in [0,160)
        sw[r * 32 + oc] = w[(ocbase + oc) * (C1 * 5) + r];
    }
    for (int i = tid; i < C1 * 132; i += 128) {
        int c = i / 132, p = i - c * 132;
        int t = t0 - 2 + p;
        sin[c][p] = (t >= 0 && t < T1) ? g_h1[(b * C1 + c) * T1 + t] : 0.f;
    }
    __syncthreads();

    const int ocg = tid & 7, pg = tid >> 3;
    const int oc0 = ocg * 4;
    const int cp0 = pg * 8;

    float acc[4][8];
#pragma unroll
    for (int a = 0; a < 4; a++) {
        float bv = bias[ocbase + oc0 + a];
#pragma unroll
        for (int p = 0; p < 8; p++) acc[a][p] = bv;
    }

    for (int c = 0; c < C1; c++) {
        float in[12];
#pragma unroll
        for (int r = 0; r < 12; r++) in[r] = sin[c][cp0 + r];
#pragma unroll
        for (int k = 0; k < 5; k++) {
            float wv[4];
#pragma unroll
            for (int a = 0; a < 4; a++) wv[a] = sw[(c * 5 + k) * 32 + oc0 + a];
#pragma unroll
            for (int a = 0; a < 4; a++)
#pragma unroll
                for (int p = 0; p < 8; p++)
                    acc[a][p] += in[p + k] * wv[a];
        }
    }

    const int pbase = blockIdx.x * 64 + pg * 4;
#pragma unroll
    for (int a = 0; a < 4; a++)
#pragma unroll
        for (int q = 0; q < 4; q++) {
            float v = fmaxf(acc[a][2 * q], acc[a][2 * q + 1]);
            v = fmaxf(v, 0.f);
            g_h2[(b * C2 + ocbase + oc0 + a) * NN + pbase + q] = v;
        }
}

// ============================================================
// hw[b][n][16] = sum_d h2[b][d][n] * gat_w[o][d];  s_src/s_dst scalars
// ============================================================
__global__ __launch_bounds__(256) void k_hw(const float* __restrict__ gw,
                                            const float* __restrict__ asrc,
                                            const float* __restrict__ adst) {
    __shared__ float4 swt4[64 * 4];          // wT[d][o] as float4 rows
    float* swt = (float*)swt4;
    const int b = blockIdx.y;
    const int n = blockIdx.x * 256 + threadIdx.x;

    for (int i = threadIdx.x; i < 1024; i += 256) {
        int o = i >> 6, d = i & 63;
        swt[d * 16 + o] = gw[i];
    }
    __syncthreads();

    float acc[16];
#pragma unroll
    for (int o = 0; o < 16; o++) acc[o] = 0.f;

    const float* h2p = &g_h2[(size_t)b * C2 * NN + n];
    for (int d = 0; d < 64; d++) {
        float v = h2p[(size_t)d * NN];
        float4 w0 = swt4[d * 4 + 0], w1 = swt4[d * 4 + 1];
        float4 w2 = swt4[d * 4 + 2], w3 = swt4[d * 4 + 3];
        acc[0]  += v * w0.x; acc[1]  += v * w0.y; acc[2]  += v * w0.z; acc[3]  += v * w0.w;
        acc[4]  += v * w1.x; acc[5]  += v * w1.y; acc[6]  += v * w1.z; acc[7]  += v * w1.w;
        acc[8]  += v * w2.x; acc[9]  += v * w2.y; acc[10] += v * w2.z; acc[11] += v * w2.w;
        acc[12] += v * w3.x; acc[13] += v * w3.y; acc[14] += v * w3.z; acc[15] += v * w3.w;
    }

    float ss = 0.f, sd = 0.f;
#pragma unroll
    for (int o = 0; o < 16; o++) {
        ss += acc[o] * __ldg(&asrc[o]);
        sd += acc[o] * __ldg(&adst[o]);
    }

    float4* outp = (float4*)&g_hw[(size_t)(b * NN + n) * 16];
    outp[0] = make_float4(acc[0], acc[1], acc[2], acc[3]);
    outp[1] = make_float4(acc[4], acc[5], acc[6], acc[7]);
    outp[2] = make_float4(acc[8], acc[9], acc[10], acc[11]);
    outp[3] = make_float4(acc[12], acc[13], acc[14], acc[15]);
    g_ssrc[b * NN + n] = ss;
    g_sdst[b * NN + n] = sd;
}

// ============================================================
// Fused factorized GAT + node-mean + FC. One block per batch sample.
//
// e_ij = lrelu(sd_i + ss_j) is rank-1 through a monotone piecewise-linear
// map, so after sorting ss ascending the row-i softmax aggregate is:
//   j >= k_i (e>=0): exp(sd_i+Mss-m_i) * suffix_{k_i}[ exp(ss_j-Mss)*hv_j ]
//   j <  k_i (e< 0): exp(0.2(sd_i+Mss)-m_i) * prefix_{k_i}[ exp(0.2(ss_j-Mss))*hv_j ]
// where hv_j = [hw_j(16), 1], m_i = lrelu(sd_i+Mss), k_i = lower_bound(-sd_i).
// All exp args <= 0. Duplicated self-loop added explicitly (PyG semantics).
// ============================================================
struct GatSmem {
    float key[NN];              // sorted ss
    int   idx[NN];              // permutation
    float scan[17][NN + 2];     // 16 dims + den; reused for prefix then suffix
    float wred[32][DG];         // per-warp partial pooled sums
    float pooled[DG];
};

__global__ __launch_bounds__(1024) void k_gat2(const float* __restrict__ gat_b,
                                               const float* __restrict__ fcw,
                                               const float* __restrict__ fcb,
                                               float* __restrict__ out) {
    extern __shared__ char smraw[];
    GatSmem& sm = *reinterpret_cast<GatSmem*>(smraw);
    const int b   = blockIdx.x;
    const int tid = threadIdx.x;

    // ---- load keys ----
    sm.key[tid] = g_ssrc[b * NN + tid];
    sm.idx[tid] = tid;

    // ---- bitonic sort ascending (key, idx). Each pair owned by one thread. ----
    for (int k = 2; k <= NN; k <<= 1) {
        for (int j = k >> 1; j > 0; j >>= 1) {
            __syncthreads();
            int partner = tid ^ j;
            if (partner > tid) {
                bool up = ((tid & k) == 0);
                float k0 = sm.key[tid], k1 = sm.key[partner];
                if ((k0 > k1) == up) {
                    sm.key[tid] = k1; sm.key[partner] = k0;
                    int t0 = sm.idx[tid];
                    sm.idx[tid] = sm.idx[partner];
                    sm.idx[partner] = t0;
                }
            }
        }
    }
    __syncthreads();

    const float Mss = sm.key[NN - 1];                 // max ss
    const int   i   = tid;                            // my destination node
    const float sd  = g_sdst[b * NN + i];
    const float ssi = g_ssrc[b * NN + i];
    const float msd = sd + Mss;
    const float m   = (msd >= 0.f) ? msd : 0.2f * msd;

    // binary search: first k with key[k] >= -sd  (those j take the e>=0 branch)
    int lo = 0, hi = NN;
    {
        const float thr = -sd;
        while (lo < hi) {
            int mid = (lo + hi) >> 1;
            if (sm.key[mid] < thr) lo = mid + 1; else hi = mid;
        }
    }
    const int kth = lo;

    float num[16];
    float den;

    // ================= Phase B: prefix of exp(0.2*(ss_j - Mss)) * hv =================
    {
        float bj = __expf(0.2f * (sm.key[tid] - Mss));
        const float4* hp = (const float4*)&g_hw[((size_t)b * NN + sm.idx[tid]) * DG];
        float4 h0 = hp[0], h1 = hp[1], h2 = hp[2], h3 = hp[3];
        sm.scan[0][tid]  = bj * h0.x; sm.scan[1][tid]  = bj * h0.y;
        sm.scan[2][tid]  = bj * h0.z; sm.scan[3][tid]  = bj * h0.w;
        sm.scan[4][tid]  = bj * h1.x; sm.scan[5][tid]  = bj * h1.y;
        sm.scan[6][tid]  = bj * h1.z; sm.scan[7][tid]  = bj * h1.w;
        sm.scan[8][tid]  = bj * h2.x; sm.scan[9][tid]  = bj * h2.y;
        sm.scan[10][tid] = bj * h2.z; sm.scan[11][tid] = bj * h2.w;
        sm.scan[12][tid] = bj * h3.x; sm.scan[13][tid] = bj * h3.y;
        sm.scan[14][tid] = bj * h3.z; sm.scan[15][tid] = bj * h3.w;
        sm.scan[16][tid] = bj;
    }
    __syncthreads();
    if (tid < 17) {                                   // exclusive prefix scan per row
        float* row = sm.scan[tid];
        float acc = 0.f;
#pragma unroll 4
        for (int j = 0; j < NN; j++) { float t = row[j]; row[j] = acc; acc += t; }
        row[NN] = acc;
    }
    __syncthreads();
    {
        float wB = __expf(0.2f * msd - m);
#pragma unroll
        for (int o = 0; o < 16; o++) num[o] = wB * sm.scan[o][kth];
        den = wB * sm.scan[16][kth];
    }
    __syncthreads();                                  // before buffer reuse

    // ================= Phase A: suffix of exp(ss_j - Mss) * hv =================
    {
        float aj = __expf(sm.key[tid] - Mss);
        const float4* hp = (const float4*)&g_hw[((size_t)b * NN + sm.idx[tid]) * DG];
        float4 h0 = hp[0], h1 = hp[1], h2 = hp[2], h3 = hp[3];
        sm.scan[0][tid]  = aj * h0.x; sm.scan[1][tid]  = aj * h0.y;
        sm.scan[2][tid]  = aj * h0.z; sm.scan[3][tid]  = aj * h0.w;
        sm.scan[4][tid]  = aj * h1.x; sm.scan[5][tid]  = aj * h1.y;
        sm.scan[6][tid]  = aj * h1.z; sm.scan[7][tid]  = aj * h1.w;
        sm.scan[8][tid]  = aj * h2.x; sm.scan[9][tid]  = aj * h2.y;
        sm.scan[10][tid] = aj * h2.z; sm.scan[11][tid] = aj * h2.w;
        sm.scan[12][tid] = aj * h3.x; sm.scan[13][tid] = aj * h3.y;
        sm.scan[14][tid] = aj * h3.z; sm.scan[15][tid] = aj * h3.w;
        sm.scan[16][tid] = aj;
    }
    __syncthreads();
    if (tid < 17) {                                   // inclusive suffix scan per row
        float* row = sm.scan[tid];
        float acc = 0.f;
        row[NN] = 0.f;
#pragma unroll 4
        for (int j = NN - 1; j >= 0; j--) { acc += row[j]; row[j] = acc; }
    }
    __syncthreads();
    {
        float wA = __expf(msd - m);
#pragma unroll
        for (int o = 0; o < 16; o++) num[o] += wA * sm.scan[o][kth];
        den += wA * sm.scan[16][kth];
    }

    // ---- duplicated self-loop (PyG add_self_loops on dense edge list) ----
    {
        float e = sd + ssi;
        e = (e >= 0.f) ? e : 0.2f * e;
        float ws = __expf(e - m);
        den += ws;
        const float4* hp = (const float4*)&g_hw[((size_t)b * NN + i) * DG];
        float4 h0 = hp[0], h1 = hp[1], h2 = hp[2], h3 = hp[3];
        num[0]  += ws * h0.x; num[1]  += ws * h0.y; num[2]  += ws * h0.z; num[3]  += ws * h0.w;
        num[4]  += ws * h1.x; num[5]  += ws * h1.y; num[6]  += ws * h1.z; num[7]  += ws * h1.w;
        num[8]  += ws * h2.x; num[9]  += ws * h2.y; num[10] += ws * h2.z; num[11] += ws * h2.w;
        num[12] += ws * h3.x; num[13] += ws * h3.y; num[14] += ws * h3.z; num[15] += ws * h3.w;
    }

    const float inv = 1.f / den;
#pragma unroll
    for (int o = 0; o < 16; o++) num[o] *= inv;       // out_i[o], bias deferred

    // ---- block reduce over 1024 nodes -> pooled[16] -> fc -> out[b][2] ----
#pragma unroll
    for (int o = 0; o < 16; o++) {
        float v = num[o];
        v += __shfl_xor_sync(0xffffffffu, v, 16);
        v += __shfl_xor_sync(0xffffffffu, v, 8);
        v += __shfl_xor_sync(0xffffffffu, v, 4);
        v += __shfl_xor_sync(0xffffffffu, v, 2);
        v += __shfl_xor_sync(0xffffffffu, v, 1);
        if ((tid & 31) == 0) sm.wred[tid >> 5][o] = v;
    }
    __syncthreads();
    if (tid < 16) {
        float s = 0.f;
        for (int w = 0; w < 32; w++) s += sm.wred[w][tid];
        sm.pooled[tid] = s * (1.0f / (float)NN) + __ldg(&gat_b[tid]);
    }
    __syncthreads();
    if (tid < 2) {
        float r = __ldg(&fcb[tid]);
#pragma unroll
        for (int o = 0; o < 16; o++) r += sm.pooled[o] * __ldg(&fcw[tid * 16 + o]);
        out[b * 2 + tid] = r;
    }
}

extern "C" void kernel_launch(void* const* d_in, const int* in_sizes, int n_in,
                              void* d_out, int out_size) {
    const float* x    = (const float*)d_in[0];
    const float* c1w  = (const float*)d_in[1];
    const float* c1b  = (const float*)d_in[2];
    const float* c2w  = (const float*)d_in[3];
    const float* c2b  = (const float*)d_in[4];
    const float* gw   = (const float*)d_in[5];
    const float* asrc = (const float*)d_in[6];
    const float* adst = (const float*)d_in[7];
    const float* gb   = (const float*)d_in[8];
    const float* fcw  = (const float*)d_in[9];
    const float* fcb  = (const float*)d_in[10];
    float* out = (float*)d_out;

    k_conv1<<<dim3(32, BATCH), 128>>>(x, c1w, c1b);
    k_conv2<<<dim3(16, BATCH, 2), 128>>>(c2w, c2b);
    k_hw<<<dim3(4, BATCH), 256>>>(gw, asrc, adst);

    // dynamic smem > 48KB: set attribute every call (deterministic, capture-safe)
    cudaFuncSetAttribute(k_gat2, cudaFuncAttributeMaxDynamicSharedMemorySize,
                         (int)sizeof(GatSmem));
    k_gat2<<<BATCH, 1024, sizeof(GatSmem)>>>(gb, fcw, fcb, out);
}

// round 10
// speedup vs baseline: 1.7150x; 1.0743x over previous
#include <cuda_runtime.h>

// Problem constants
#define BATCH 128
#define CIN   17
#define TIN   4096
#define C1    32
#define T1    2048   // after pool1
#define C2    64
#define NN    1024   // nodes after pool2
#define DG    16     // GAT out dim

typedef unsigned long long ull;

// ---- packed f32x2 helpers (FFMA2 path; ptxas won't auto-fuse) ----
__device__ __forceinline__ ull pack2(float lo, float hi) {
    ull v; asm("mov.b64 %0, {%1, %2};" : "=l"(v) : "f"(lo), "f"(hi)); return v;
}
__device__ __forceinline__ void unpack2(ull v, float& lo, float& hi) {
    asm("mov.b64 {%0, %1}, %2;" : "=f"(lo), "=f"(hi) : "l"(v));
}
__device__ __forceinline__ ull ffma2(ull a, ull b, ull c) {
    ull d; asm("fma.rn.f32x2 %0, %1, %2, %3;" : "=l"(d) : "l"(a), "l"(b), "l"(c));
    return d;
}

// ---- scratch (static device allocations; no cudaMalloc anywhere) ----
__device__ float g_h1[BATCH * C1 * T1];     // 33.5 MB
__device__ float g_hw[BATCH * NN * DG];     // 8.4 MB
__device__ float g_ssrc[BATCH * NN];
__device__ float g_sdst[BATCH * NN];

// ============================================================
// conv1: x[b][17][4096] -> relu -> maxpool2 -> g_h1[b][32][2048]
// FFMA2 over output-channel pairs; weights transposed in smem so a
// channel pair is one aligned LDS.64.
// ============================================================
__global__ __launch_bounds__(128) void k_conv1(const float* __restrict__ x,
                                               const float* __restrict__ w,
                                               const float* __restrict__ bias) {
    __shared__ float sinp[CIN][132];               // 128 conv pos + 4 halo
    __shared__ __align__(16) float sw[85 * 32];    // [(c*5+k)][oc] transposed
    const int b   = blockIdx.y;
    const int t0  = blockIdx.x * 128;
    const int tid = threadIdx.x;

    for (int i = tid; i < 85 * 32; i += 128) {
        int oc = i & 31, r = i >> 5;
        sw[r * 32 + oc] = w[oc * 85 + r];
    }
    for (int i = tid; i < CIN * 132; i += 128) {
        int c = i / 132, p = i - c * 132;
        int t = t0 - 2 + p;
        sinp[c][p] = (t >= 0 && t < TIN) ? x[(b * CIN + c) * TIN + t] : 0.f;
    }
    __syncthreads();

    const int ocg = tid & 7, pg = tid >> 3;
    const int oc0 = ocg * 4;                       // 4 ocs = 2 packed pairs
    const int cp0 = pg * 8;                        // 8 conv positions

    ull acc2[2][8];
    {
        ull b0 = pack2(bias[oc0],     bias[oc0 + 1]);
        ull b1 = pack2(bias[oc0 + 2], bias[oc0 + 3]);
#pragma unroll
        for (int p = 0; p < 8; p++) { acc2[0][p] = b0; acc2[1][p] = b1; }
    }

    for (int c = 0; c < CIN; c++) {
        ull bb[12];
#pragma unroll
        for (int r = 0; r < 12; r++) {
            float v = sinp[c][cp0 + r];
            bb[r] = pack2(v, v);
        }
#pragma unroll
        for (int k = 0; k < 5; k++) {
            const float* wp = &sw[(c * 5 + k) * 32 + oc0];
            ull w0 = *reinterpret_cast<const ull*>(wp);
            ull w1 = *reinterpret_cast<const ull*>(wp + 2);
#pragma unroll
            for (int p = 0; p < 8; p++) {
                acc2[0][p] = ffma2(bb[p + k], w0, acc2[0][p]);
                acc2[1][p] = ffma2(bb[p + k], w1, acc2[1][p]);
            }
        }
    }

    const int pbase = blockIdx.x * 64 + pg * 4;
#pragma unroll
    for (int a2 = 0; a2 < 2; a2++)
#pragma unroll
        for (int q = 0; q < 4; q++) {
            float lo0, hi0, lo1, hi1;
            unpack2(acc2[a2][2 * q],     lo0, hi0);
            unpack2(acc2[a2][2 * q + 1], lo1, hi1);
            int oc = oc0 + 2 * a2;
            g_h1[(b * C1 + oc)     * T1 + pbase + q] = fmaxf(fmaxf(lo0, lo1), 0.f);
            g_h1[(b * C1 + oc + 1) * T1 + pbase + q] = fmaxf(fmaxf(hi0, hi1), 0.f);
        }
}

// ============================================================
// conv2 FUSED: g_h1 -> conv(32->64,k5) -> relu -> maxpool2 -> (smem tile)
//   -> hw = h2 @ gat_wT, s_src, s_dst   (g_h2 eliminated, k_hw eliminated)
// One block = 64 output channels x 64 nodes (128 conv positions).
// Two weight halves streamed through one smem buffer; FFMA2 mainloop.
// ============================================================
struct Conv2Sm {
    union {
        float  sinp[C1][132];            // 16896 B  (phase 1)
        float4 wt4[64 * 4];              //  4096 B  (epilogue: wT[d][o])
    } A;
    union {
        float sw[160 * 32];              // 20480 B  (phase 1, per oc-half)
        struct {
            float h2s[64][65];           // 16640 B  (epilogue, pad 65 vs conflicts)
            float red[2][64][4];         //  2048 B
        } ep;
    } B;
};

__global__ __launch_bounds__(256) void k_conv2(const float* __restrict__ w,
                                               const float* __restrict__ bias,
                                               const float* __restrict__ gw,
                                               const float* __restrict__ asrc,
                                               const float* __restrict__ adst) {
    __shared__ __align__(16) Conv2Sm cs;
    const int b   = blockIdx.y;
    const int t0  = blockIdx.x * 128;
    const int tid = threadIdx.x;
    const int ocg = tid & 7, pg = tid >> 3;        // pg in [0,32)
    const int oc0 = ocg * 4;
    const int cp0 = pg * 4;                        // 4 conv positions

    for (int i = tid; i < C1 * 132; i += 256) {
        int c = i / 132, p = i - c * 132;
        int t = t0 - 2 + p;
        cs.A.sinp[c][p] = (t >= 0 && t < T1) ? g_h1[(b * C1 + c) * T1 + t] : 0.f;
    }

    ull acc2[2][2][4];
#pragma unroll
    for (int h = 0; h < 2; h++) {
        ull b0 = pack2(bias[h * 32 + oc0],     bias[h * 32 + oc0 + 1]);
        ull b1 = pack2(bias[h * 32 + oc0 + 2], bias[h * 32 + oc0 + 3]);
#pragma unroll
        for (int p = 0; p < 4; p++) { acc2[h][0][p] = b0; acc2[h][1][p] = b1; }
    }

#pragma unroll
    for (int h = 0; h < 2; h++) {
        __syncthreads();                           // sw buffer free / sin loaded
        for (int i = tid; i < 160 * 32; i += 256) {
            int oc = i & 31, r = i >> 5;
            cs.B.sw[r * 32 + oc] = w[(h * 32 + oc) * 160 + r];
        }
        __syncthreads();

        for (int c = 0; c < C1; c++) {
            ull bb[8];
#pragma unroll
            for (int r = 0; r < 8; r++) {
                float v = cs.A.sinp[c][cp0 + r];
                bb[r] = pack2(v, v);
            }
#pragma unroll
            for (int k = 0; k < 5; k++) {
                const float* wp = &cs.B.sw[(c * 5 + k) * 32 + oc0];
                ull w0 = *reinterpret_cast<const ull*>(wp);
                ull w1 = *reinterpret_cast<const ull*>(wp + 2);
#pragma unroll
                for (int p = 0; p < 4; p++) {
                    acc2[h][0][p] = ffma2(bb[p + k], w0, acc2[h][0][p]);
                    acc2[h][1][p] = ffma2(bb[p + k], w1, acc2[h][1][p]);
                }
            }
        }
    }
    __syncthreads();                               // all sw/sin reads done

    // pooled relu -> smem h2 tile; concurrently load wT
#pragma unroll
    for (int h = 0; h < 2; h++)
#pragma unroll
        for (int a2 = 0; a2 < 2; a2++)
#pragma unroll
            for (int q = 0; q < 2; q++) {
                float lo0, hi0, lo1, hi1;
                unpack2(acc2[h][a2][2 * q],     lo0, hi0);
                unpack2(acc2[h][a2][2 * q + 1], lo1, hi1);
                int node = pg * 2 + q;
                int oc   = h * 32 + oc0 + 2 * a2;
                cs.B.ep.h2s[node][oc]     = fmaxf(fmaxf(lo0, lo1), 0.f);
                cs.B.ep.h2s[node][oc + 1] = fmaxf(fmaxf(hi0, hi1), 0.f);
            }
    {
        float* wt = (float*)cs.A.wt4;              // wt[d*16+o]
        for (int i = tid; i < 1024; i += 256) {
            int o = i >> 6, d = i & 63;
            wt[d * 16 + o] = gw[i];
        }
    }
    __syncthreads();

    // epilogue: hw[node][og*4..+3] = sum_d h2s[node][d] * wT[d][..]
    const int node = tid & 63;
    const int og   = tid >> 6;
    float acc[4] = {0.f, 0.f, 0.f, 0.f};
#pragma unroll 4
    for (int d = 0; d < 64; d++) {
        float v = cs.B.ep.h2s[node][d];
        float4 w4 = cs.A.wt4[d * 4 + og];
        acc[0] += v * w4.x; acc[1] += v * w4.y;
        acc[2] += v * w4.z; acc[3] += v * w4.w;
    }
    const int ngl = blockIdx.x * 64 + node;
    ((float4*)&g_hw[((size_t)b * NN + ngl) * DG])[og] =
        make_float4(acc[0], acc[1], acc[2], acc[3]);

    float ps = 0.f, pd = 0.f;
#pragma unroll
    for (int u = 0; u < 4; u++) {
        ps += acc[u] * __ldg(&asrc[og * 4 + u]);
        pd += acc[u] * __ldg(&adst[og * 4 + u]);
    }
    cs.B.ep.red[0][node][og] = ps;
    cs.B.ep.red[1][node][og] = pd;
    __syncthreads();
    if (tid < 64) {
        float s = cs.B.ep.red[0][tid][0] + cs.B.ep.red[0][tid][1]
                + cs.B.ep.red[0][tid][2] + cs.B.ep.red[0][tid][3];
        float d = cs.B.ep.red[1][tid][0] + cs.B.ep.red[1][tid][1]
                + cs.B.ep.red[1][tid][2] + cs.B.ep.red[1][tid][3];
        g_ssrc[b * NN + blockIdx.x * 64 + tid] = s;
        g_sdst[b * NN + blockIdx.x * 64 + tid] = d;
    }
}

// ============================================================
// Fused factorized GAT + node-mean + FC. One block per batch sample.
// (unchanged from R8 — rank-1 lrelu factorization via sort + prefix/suffix)
// ============================================================
struct GatSmem {
    float key[NN];              // sorted ss
    int   idx[NN];              // permutation
    float scan[17][NN + 2];     // 16 dims + den; reused for prefix then suffix
    float wred[32][DG];         // per-warp partial pooled sums
    float pooled[DG];
};

__global__ __launch_bounds__(1024) void k_gat2(const float* __restrict__ gat_b,
                                               const float* __restrict__ fcw,
                                               const float* __restrict__ fcb,
                                               float* __restrict__ out) {
    extern __shared__ char smraw[];
    GatSmem& sm = *reinterpret_cast<GatSmem*>(smraw);
    const int b   = blockIdx.x;
    const int tid = threadIdx.x;

    sm.key[tid] = g_ssrc[b * NN + tid];
    sm.idx[tid] = tid;

    // bitonic sort ascending (key, idx)
    for (int k = 2; k <= NN; k <<= 1) {
        for (int j = k >> 1; j > 0; j >>= 1) {
            __syncthreads();
            int partner = tid ^ j;
            if (partner > tid) {
                bool up = ((tid & k) == 0);
                float k0 = sm.key[tid], k1 = sm.key[partner];
                if ((k0 > k1) == up) {
                    sm.key[tid] = k1; sm.key[partner] = k0;
                    int t0 = sm.idx[tid];
                    sm.idx[tid] = sm.idx[partner];
                    sm.idx[partner] = t0;
                }
            }
        }
    }
    __syncthreads();

    const float Mss = sm.key[NN - 1];
    const int   i   = tid;
    const float sd  = g_sdst[b * NN + i];
    const float ssi = g_ssrc[b * NN + i];
    const float msd = sd + Mss;
    const float m   = (msd >= 0.f) ? msd : 0.2f * msd;

    int lo = 0, hi = NN;
    {
        const float thr = -sd;
        while (lo < hi) {
            int mid = (lo + hi) >> 1;
            if (sm.key[mid] < thr) lo = mid + 1; else hi = mid;
        }
    }
    const int kth = lo;

    float num[16];
    float den;

    // Phase B: prefix of exp(0.2*(ss_j - Mss)) * hv
    {
        float bj = __expf(0.2f * (sm.key[tid] - Mss));
        const float4* hp = (const float4*)&g_hw[((size_t)b * NN + sm.idx[tid]) * DG];
        float4 h0 = hp[0], h1 = hp[1], h2 = hp[2], h3 = hp[3];
        sm.scan[0][tid]  = bj * h0.x; sm.scan[1][tid]  = bj * h0.y;
        sm.scan[2][tid]  = bj * h0.z; sm.scan[3][tid]  = bj * h0.w;
        sm.scan[4][tid]  = bj * h1.x; sm.scan[5][tid]  = bj * h1.y;
        sm.scan[6][tid]  = bj * h1.z; sm.scan[7][tid]  = bj * h1.w;
        sm.scan[8][tid]  = bj * h2.x; sm.scan[9][tid]  = bj * h2.y;
        sm.scan[10][tid] = bj * h2.z; sm.scan[11][tid] = bj * h2.w;
        sm.scan[12][tid] = bj * h3.x; sm.scan[13][tid] = bj * h3.y;
        sm.scan[14][tid] = bj * h3.z; sm.scan[15][tid] = bj * h3.w;
        sm.scan[16][tid] = bj;
    }
    __syncthreads();
    if (tid < 17) {
        float* row = sm.scan[tid];
        float acc = 0.f;
#pragma unroll 4
        for (int j = 0; j < NN; j++) { float t = row[j]; row[j] = acc; acc += t; }
        row[NN] = acc;
    }
    __syncthreads();
    {
        float wB = __expf(0.2f * msd - m);
#pragma unroll
        for (int o = 0; o < 16; o++) num[o] = wB * sm.scan[o][kth];
        den = wB * sm.scan[16][kth];
    }
    __syncthreads();

    // Phase A: suffix of exp(ss_j - Mss) * hv
    {
        float aj = __expf(sm.key[tid] - Mss);
        const float4* hp = (const float4*)&g_hw[((size_t)b * NN + sm.idx[tid]) * DG];
        float4 h0 = hp[0], h1 = hp[1], h2 = hp[2], h3 = hp[3];
        sm.scan[0][tid]  = aj * h0.x; sm.scan[1][tid]  = aj * h0.y;
        sm.scan[2][tid]  = aj * h0.z; sm.scan[3][tid]  = aj * h0.w;
        sm.scan[4][tid]  = aj * h1.x; sm.scan[5][tid]  = aj * h1.y;
        sm.scan[6][tid]  = aj * h1.z; sm.scan[7][tid]  = aj * h1.w;
        sm.scan[8][tid]  = aj * h2.x; sm.scan[9][tid]  = aj * h2.y;
        sm.scan[10][tid] = aj * h2.z; sm.scan[11][tid] = aj * h2.w;
        sm.scan[12][tid] = aj * h3.x; sm.scan[13][tid] = aj * h3.y;
        sm.scan[14][tid] = aj * h3.z; sm.scan[15][tid] = aj * h3.w;
        sm.scan[16][tid] = aj;
    }
    __syncthreads();
    if (tid < 17) {
        float* row = sm.scan[tid];
        float acc = 0.f;
        row[NN] = 0.f;
#pragma unroll 4
        for (int j = NN - 1; j >= 0; j--) { acc += row[j]; row[j] = acc; }
    }
    __syncthreads();
    {
        float wA = __expf(msd - m);
#pragma unroll
        for (int o = 0; o < 16; o++) num[o] += wA * sm.scan[o][kth];
        den += wA * sm.scan[16][kth];
    }

    // duplicated self-loop (PyG add_self_loops on dense edge list)
    {
        float e = sd + ssi;
        e = (e >= 0.f) ? e : 0.2f * e;
        float ws = __expf(e - m);
        den += ws;
        const float4* hp = (const float4*)&g_hw[((size_t)b * NN + i) * DG];
        float4 h0 = hp[0], h1 = hp[1], h2 = hp[2], h3 = hp[3];
        num[0]  += ws * h0.x; num[1]  += ws * h0.y; num[2]  += ws * h0.z; num[3]  += ws * h0.w;
        num[4]  += ws * h1.x; num[5]  += ws * h1.y; num[6]  += ws * h1.z; num[7]  += ws * h1.w;
        num[8]  += ws * h2.x; num[9]  += ws * h2.y; num[10] += ws * h2.z; num[11] += ws * h2.w;
        num[12] += ws * h3.x; num[13] += ws * h3.y; num[14] += ws * h3.z; num[15] += ws * h3.w;
    }

    const float inv = 1.f / den;
#pragma unroll
    for (int o = 0; o < 16; o++) num[o] *= inv;

    // block reduce over 1024 nodes -> pooled[16] -> fc -> out[b][2]
#pragma unroll
    for (int o = 0; o < 16; o++) {
        float v = num[o];
        v += __shfl_xor_sync(0xffffffffu, v, 16);
        v += __shfl_xor_sync(0xffffffffu, v, 8);
        v += __shfl_xor_sync(0xffffffffu, v, 4);
        v += __shfl_xor_sync(0xffffffffu, v, 2);
        v += __shfl_xor_sync(0xffffffffu, v, 1);
        if ((tid & 31) == 0) sm.wred[tid >> 5][o] = v;
    }
    __syncthreads();
    if (tid < 16) {
        float s = 0.f;
        for (int w = 0; w < 32; w++) s += sm.wred[w][tid];
        sm.pooled[tid] = s * (1.0f / (float)NN) + __ldg(&gat_b[tid]);
    }
    __syncthreads();
    if (tid < 2) {
        float r = __ldg(&fcb[tid]);
#pragma unroll
        for (int o = 0; o < 16; o++) r += sm.pooled[o] * __ldg(&fcw[tid * 16 + o]);
        out[b * 2 + tid] = r;
    }
}

extern "C" void kernel_launch(void* const* d_in, const int* in_sizes, int n_in,
                              void* d_out, int out_size) {
    const float* x    = (const float*)d_in[0];
    const float* c1w  = (const float*)d_in[1];
    const float* c1b  = (const float*)d_in[2];
    const float* c2w  = (const float*)d_in[3];
    const float* c2b  = (const float*)d_in[4];
    const float* gw   = (const float*)d_in[5];
    const float* asrc = (const float*)d_in[6];
    const float* adst = (const float*)d_in[7];
    const float* gb   = (const float*)d_in[8];
    const float* fcw  = (const float*)d_in[9];
    const float* fcb  = (const float*)d_in[10];
    float* out = (float*)d_out;

    k_conv1<<<dim3(32, BATCH), 128>>>(x, c1w, c1b);
    k_conv2<<<dim3(16, BATCH), 256>>>(c2w, c2b, gw, asrc, adst);

    cudaFuncSetAttribute(k_gat2, cudaFuncAttributeMaxDynamicSharedMemorySize,
                         (int)sizeof(GatSmem));
    k_gat2<<<BATCH, 1024, sizeof(GatSmem)>>>(gb, fcw, fcb, out);
}

// round 11
// speedup vs baseline: 1.8524x; 1.0802x over previous
#include <cuda_runtime.h>

// Problem constants
#define BATCH 128
#define CIN   17
#define TIN   4096
#define C1    32
#define T1    2048   // after pool1
#define C2    64
#define NN    1024   // nodes after pool2
#define DG    16     // GAT out dim

typedef unsigned long long ull;

// ---- packed f32x2 helpers (FFMA2 path; ptxas won't auto-fuse) ----
__device__ __forceinline__ ull pack2(float lo, float hi) {
    ull v; asm("mov.b64 %0, {%1, %2};" : "=l"(v) : "f"(lo), "f"(hi)); return v;
}
__device__ __forceinline__ void unpack2(ull v, float& lo, float& hi) {
    asm("mov.b64 {%0, %1}, %2;" : "=f"(lo), "=f"(hi) : "l"(v));
}
__device__ __forceinline__ ull ffma2(ull a, ull b, ull c) {
    ull d; asm("fma.rn.f32x2 %0, %1, %2, %3;" : "=l"(d) : "l"(a), "l"(b), "l"(c));
    return d;
}

// padded scan index: stride-17 layout kills the 16-way bank conflict
__device__ __forceinline__ int IDXf(int j) { return j + (j >> 4); }

// ---- scratch (static device allocations; no cudaMalloc anywhere) ----
__device__ float g_h1[BATCH * C1 * T1];     // 33.5 MB
__device__ float g_hw[BATCH * NN * DG];     // 8.4 MB
__device__ float g_ssrc[BATCH * NN];
__device__ float g_sdst[BATCH * NN];

// ============================================================
// conv1: x[b][17][4096] -> relu -> maxpool2 -> g_h1[b][32][2048]
// Inputs stored PRE-DUPLICATED (f32x2) in smem: mainloop = LDS.64 + FFMA2
// only. All global loads vectorized LDG.128.
// ============================================================
__global__ __launch_bounds__(128) void k_conv1(const float* __restrict__ x,
                                               const float* __restrict__ w,
                                               const float* __restrict__ bias) {
    __shared__ ull sdin[CIN][132];                 // duplicated input, 17.9 KB
    __shared__ __align__(16) float sw[85 * 32];    // [(c*5+k)][oc] transposed
    const int b   = blockIdx.y;
    const int t0  = blockIdx.x * 128;
    const int tid = threadIdx.x;

    // weights: 2720 floats = 680 float4, scatter to transposed layout
    {
        const float4* w4 = (const float4*)w;
        for (int i = tid; i < 680; i += 128) {
            float4 v = w4[i];
            int f = i * 4;
#pragma unroll
            for (int u = 0; u < 4; u++) {
                int ff = f + u;
                int oc = ff / 85, r = ff - oc * 85;
                sw[r * 32 + oc] = (&v.x)[u];
            }
        }
    }
    // input body: 17 rows x 32 float4 (aligned, t0 multiple of 128)
    for (int i = tid; i < 17 * 32; i += 128) {
        int c = i >> 5, iv = i & 31;
        float4 v = *(const float4*)&x[(b * CIN + c) * TIN + t0 + iv * 4];
        int p = 2 + iv * 4;
        sdin[c][p]     = pack2(v.x, v.x);
        sdin[c][p + 1] = pack2(v.y, v.y);
        sdin[c][p + 2] = pack2(v.z, v.z);
        sdin[c][p + 3] = pack2(v.w, v.w);
    }
    // halo: 2 each side per row
    if (tid < 68) {
        int c = tid >> 2, u = tid & 3;
        int p = (u < 2) ? u : (128 + u);           // {0,1,130,131}
        int t = t0 - 2 + p;
        float v = (t >= 0 && t < TIN) ? x[(b * CIN + c) * TIN + t] : 0.f;
        sdin[c][p] = pack2(v, v);
    }
    __syncthreads();

    const int ocg = tid & 7, pg = tid >> 3;
    const int oc0 = ocg * 4;                       // 4 ocs = 2 packed pairs
    const int cp0 = pg * 8;                        // 8 conv positions

    ull acc2[2][8];
    {
        ull b0 = pack2(bias[oc0],     bias[oc0 + 1]);
        ull b1 = pack2(bias[oc0 + 2], bias[oc0 + 3]);
#pragma unroll
        for (int p = 0; p < 8; p++) { acc2[0][p] = b0; acc2[1][p] = b1; }
    }

    for (int c = 0; c < CIN; c++) {
        ull bb[12];
#pragma unroll
        for (int r = 0; r < 12; r++) bb[r] = sdin[c][cp0 + r];
#pragma unroll
        for (int k = 0; k < 5; k++) {
            const float* wp = &sw[(c * 5 + k) * 32 + oc0];
            ull w0 = *reinterpret_cast<const ull*>(wp);
            ull w1 = *reinterpret_cast<const ull*>(wp + 2);
#pragma unroll
            for (int p = 0; p < 8; p++) {
                acc2[0][p] = ffma2(bb[p + k], w0, acc2[0][p]);
                acc2[1][p] = ffma2(bb[p + k], w1, acc2[1][p]);
            }
        }
    }

    const int pbase = blockIdx.x * 64 + pg * 4;
#pragma unroll
    for (int a2 = 0; a2 < 2; a2++)
#pragma unroll
        for (int q = 0; q < 4; q++) {
            float lo0, hi0, lo1, hi1;
            unpack2(acc2[a2][2 * q],     lo0, hi0);
            unpack2(acc2[a2][2 * q + 1], lo1, hi1);
            int oc = oc0 + 2 * a2;
            g_h1[(b * C1 + oc)     * T1 + pbase + q] = fmaxf(fmaxf(lo0, lo1), 0.f);
            g_h1[(b * C1 + oc + 1) * T1 + pbase + q] = fmaxf(fmaxf(hi0, hi1), 0.f);
        }
}

// ============================================================
// conv2 FUSED: g_h1 -> conv(32->64,k5) -> relu -> maxpool2 -> (smem)
//   -> hw = h2 @ gat_wT, s_src, s_dst
// BOTH weight halves resident (no mid-kernel reload); inputs duplicated
// f32x2 in smem; input bb[] shared across both oc-halves.
// ============================================================
struct Conv2Sm {
    union {
        ull sdin[C1][132];               // 33792 B (phase 1, duplicated)
        struct {
            float h2s[64][65];           // 16640 B (epilogue, pad 65)
            float red[2][64][4];         //  2048 B
        } ep;
    } A;
    union {
        float  sw[160 * 64];             // 40960 B ([(c*5+k)][oc], both halves)
        float4 wt4[64 * 4];              //  4096 B (epilogue: wT[d][o])
    } B;
};

extern __shared__ __align__(16) char c2raw[];

__global__ __launch_bounds__(256) void k_conv2(const float* __restrict__ w,
                                               const float* __restrict__ bias,
                                               const float* __restrict__ gw,
                                               const float* __restrict__ asrc,
                                               const float* __restrict__ adst) {
    Conv2Sm& cs = *reinterpret_cast<Conv2Sm*>(c2raw);
    const int b   = blockIdx.y;
    const int t0  = blockIdx.x * 128;
    const int tid = threadIdx.x;

    // weights: 64*160 floats = 2560 float4, scatter to [(c*5+k)*64 + oc]
    {
        const float4* w4 = (const float4*)w;
        for (int i = tid; i < 2560; i += 256) {
            float4 v = w4[i];
            int f = i * 4;
#pragma unroll
            for (int u = 0; u < 4; u++) {
                int ff = f + u;
                int oc = ff / 160, r = ff - oc * 160;
                cs.B.sw[r * 64 + oc] = (&v.x)[u];
            }
        }
    }
    // input body: 32 rows x 32 float4
    for (int i = tid; i < 32 * 32; i += 256) {
        int c = i >> 5, iv = i & 31;
        float4 v = *(const float4*)&g_h1[(b * C1 + c) * T1 + t0 + iv * 4];
        int p = 2 + iv * 4;
        cs.A.sdin[c][p]     = pack2(v.x, v.x);
        cs.A.sdin[c][p + 1] = pack2(v.y, v.y);
        cs.A.sdin[c][p + 2] = pack2(v.z, v.z);
        cs.A.sdin[c][p + 3] = pack2(v.w, v.w);
    }
    if (tid < 128) {
        int c = tid >> 2, u = tid & 3;
        int p = (u < 2) ? u : (128 + u);
        int t = t0 - 2 + p;
        float v = (t >= 0 && t < T1) ? g_h1[(b * C1 + c) * T1 + t] : 0.f;
        cs.A.sdin[c][p] = pack2(v, v);
    }
    __syncthreads();

    const int ocg = tid & 7, pg = tid >> 3;        // pg in [0,32)
    const int oc0 = ocg * 4;
    const int cp0 = pg * 4;                        // 4 conv positions

    ull acc2[2][2][4];
#pragma unroll
    for (int h = 0; h < 2; h++) {
        ull b0 = pack2(bias[h * 32 + oc0],     bias[h * 32 + oc0 + 1]);
        ull b1 = pack2(bias[h * 32 + oc0 + 2], bias[h * 32 + oc0 + 3]);
#pragma unroll
        for (int p = 0; p < 4; p++) { acc2[h][0][p] = b0; acc2[h][1][p] = b1; }
    }

    for (int c = 0; c < C1; c++) {
        ull bb[8];
#pragma unroll
        for (int r = 0; r < 8; r++) bb[r] = cs.A.sdin[c][cp0 + r];
#pragma unroll
        for (int k = 0; k < 5; k++) {
            const float* wb = &cs.B.sw[(c * 5 + k) * 64];
#pragma unroll
            for (int h = 0; h < 2; h++) {
                const float* wp = wb + h * 32 + oc0;
                ull w0 = *reinterpret_cast<const ull*>(wp);
                ull w1 = *reinterpret_cast<const ull*>(wp + 2);
#pragma unroll
                for (int p = 0; p < 4; p++) {
                    acc2[h][0][p] = ffma2(bb[p + k], w0, acc2[h][0][p]);
                    acc2[h][1][p] = ffma2(bb[p + k], w1, acc2[h][1][p]);
                }
            }
        }
    }
    __syncthreads();                               // all sdin/sw reads done

    // pooled relu -> smem h2 tile; concurrently load wT into B union
#pragma unroll
    for (int h = 0; h < 2; h++)
#pragma unroll
        for (int a2 = 0; a2 < 2; a2++)
#pragma unroll
            for (int q = 0; q < 2; q++) {
                float lo0, hi0, lo1, hi1;
                unpack2(acc2[h][a2][2 * q],     lo0, hi0);
                unpack2(acc2[h][a2][2 * q + 1], lo1, hi1);
                int node = pg * 2 + q;
                int oc   = h * 32 + oc0 + 2 * a2;
                cs.A.ep.h2s[node][oc]     = fmaxf(fmaxf(lo0, lo1), 0.f);
                cs.A.ep.h2s[node][oc + 1] = fmaxf(fmaxf(hi0, hi1), 0.f);
            }
    {
        float* wt = (float*)cs.B.wt4;              // wt[d*16+o]
        for (int i = tid; i < 1024; i += 256) {
            int o = i >> 6, d = i & 63;
            wt[d * 16 + o] = gw[i];
        }
    }
    __syncthreads();

    // epilogue: hw[node][og*4..+3] = sum_d h2s[node][d] * wT[d][..]
    const int node = tid & 63;
    const int og   = tid >> 6;
    float acc[4] = {0.f, 0.f, 0.f, 0.f};
#pragma unroll 4
    for (int d = 0; d < 64; d++) {
        float v = cs.A.ep.h2s[node][d];
        float4 w4 = cs.B.wt4[d * 4 + og];
        acc[0] += v * w4.x; acc[1] += v * w4.y;
        acc[2] += v * w4.z; acc[3] += v * w4.w;
    }
    const int ngl = blockIdx.x * 64 + node;
    ((float4*)&g_hw[((size_t)b * NN + ngl) * DG])[og] =
        make_float4(acc[0], acc[1], acc[2], acc[3]);

    float ps = 0.f, pd = 0.f;
#pragma unroll
    for (int u = 0; u < 4; u++) {
        ps += acc[u] * __ldg(&asrc[og * 4 + u]);
        pd += acc[u] * __ldg(&adst[og * 4 + u]);
    }
    cs.A.ep.red[0][node][og] = ps;
    cs.A.ep.red[1][node][og] = pd;
    __syncthreads();
    if (tid < 64) {
        float s = cs.A.ep.red[0][tid][0] + cs.A.ep.red[0][tid][1]
                + cs.A.ep.red[0][tid][2] + cs.A.ep.red[0][tid][3];
        float d = cs.A.ep.red[1][tid][0] + cs.A.ep.red[1][tid][1]
                + cs.A.ep.red[1][tid][2] + cs.A.ep.red[1][tid][3];
        g_ssrc[b * NN + blockIdx.x * 64 + tid] = s;
        g_sdst[b * NN + blockIdx.x * 64 + tid] = d;
    }
}

// ============================================================
// Fused factorized GAT + node-mean + FC. One block per batch sample.
// Scans now parallel: 64 threads/row, 16-elem register-serial chunks +
// shfl cross-chunk combine; padded index IDXf kills bank conflicts.
// ============================================================
struct GatSmem {
    float key[NN];              // sorted ss
    int   idx[NN];              // permutation
    float scan[17][1090];       // padded rows (IDXf), reused prefix/suffix
    float wtot[17][2];          // per-row warp totals for chunk combine
    float wred[32][DG];         // per-warp partial pooled sums
    float pooled[DG];
};

__global__ __launch_bounds__(1024) void k_gat2(const float* __restrict__ gat_b,
                                               const float* __restrict__ fcw,
                                               const float* __restrict__ fcb,
                                               float* __restrict__ out) {
    extern __shared__ __align__(16) char smraw[];
    GatSmem& sm = *reinterpret_cast<GatSmem*>(smraw);
    const int b   = blockIdx.x;
    const int tid = threadIdx.x;

    sm.key[tid] = g_ssrc[b * NN + tid];
    sm.idx[tid] = tid;

    // bitonic sort ascending (key, idx)
    for (int k = 2; k <= NN; k <<= 1) {
        for (int j = k >> 1; j > 0; j >>= 1) {
            __syncthreads();
            int partner = tid ^ j;
            if (partner > tid) {
                bool up = ((tid & k) == 0);
                float k0 = sm.key[tid], k1 = sm.key[partner];
                if ((k0 > k1) == up) {
                    sm.key[tid] = k1; sm.key[partner] = k0;
                    int t0 = sm.idx[tid];
                    sm.idx[tid] = sm.idx[partner];
                    sm.idx[partner] = t0;
                }
            }
        }
    }
    __syncthreads();

    const float Mss = sm.key[NN - 1];
    const int   i   = tid;
    const float sd  = g_sdst[b * NN + i];
    const float ssi = g_ssrc[b * NN + i];
    const float msd = sd + Mss;
    const float m   = (msd >= 0.f) ? msd : 0.2f * msd;

    int lo = 0, hi = NN;
    {
        const float thr = -sd;
        while (lo < hi) {
            int mid = (lo + hi) >> 1;
            if (sm.key[mid] < thr) lo = mid + 1; else hi = mid;
        }
    }
    const int kth  = lo;
    const int kthx = IDXf(kth);
    const int tix  = IDXf(tid);

    // scan-worker coordinates
    const int sr   = tid >> 6;                 // row 0..15
    const int sc   = tid & 63;                 // chunk within row
    const int lane = sc & 31;
    const int wir  = sc >> 5;                  // warp-in-row
    const int rb   = sc * 17;                  // IDXf(sc*16)

    float num[16];
    float den;

    // ======== Phase B: exclusive prefix of exp(0.2*(ss_j - Mss)) * hv ========
    {
        float bj = __expf(0.2f * (sm.key[tid] - Mss));
        const float4* hp = (const float4*)&g_hw[((size_t)b * NN + sm.idx[tid]) * DG];
        float4 h0 = hp[0], h1 = hp[1], h2 = hp[2], h3 = hp[3];
        sm.scan[0][tix]  = bj * h0.x; sm.scan[1][tix]  = bj * h0.y;
        sm.scan[2][tix]  = bj * h0.z; sm.scan[3][tix]  = bj * h0.w;
        sm.scan[4][tix]  = bj * h1.x; sm.scan[5][tix]  = bj * h1.y;
        sm.scan[6][tix]  = bj * h1.z; sm.scan[7][tix]  = bj * h1.w;
        sm.scan[8][tix]  = bj * h2.x; sm.scan[9][tix]  = bj * h2.y;
        sm.scan[10][tix] = bj * h2.z; sm.scan[11][tix] = bj * h2.w;
        sm.scan[12][tix] = bj * h3.x; sm.scan[13][tix] = bj * h3.y;
        sm.scan[14][tix] = bj * h3.z; sm.scan[15][tix] = bj * h3.w;
        sm.scan[16][tix] = bj;
    }
    __syncthreads();
    {
        // pass 1: chunk sums + warp inclusive scans
        float* row = sm.scan[sr];
        float s = 0.f;
#pragma unroll
        for (int u = 0; u < 16; u++) s += row[rb + u];
        float inc = s;
#pragma unroll
        for (int o = 1; o < 32; o <<= 1) {
            float v = __shfl_up_sync(0xffffffffu, inc, o);
            if (lane >= o) inc += v;
        }
        if (lane == 31) sm.wtot[sr][wir] = inc;

        float s2 = 0.f, inc2 = 0.f;
        if (tid < 64) {                            // den row (16), warps 0-1
            float* drow = sm.scan[16];
            int drb = tid * 17;
#pragma unroll
            for (int u = 0; u < 16; u++) s2 += drow[drb + u];
            inc2 = s2;
#pragma unroll
            for (int o = 1; o < 32; o <<= 1) {
                float v = __shfl_up_sync(0xffffffffu, inc2, o);
                if ((tid & 31) >= o) inc2 += v;
            }
            if ((tid & 31) == 31) sm.wtot[16][tid >> 5] = inc2;
        }
        __syncthreads();

        // pass 2: apply exclusive offsets
        float off = inc - s + ((wir == 1) ? sm.wtot[sr][0] : 0.f);
        float acc = off;
#pragma unroll
        for (int u = 0; u < 16; u++) {
            float t = row[rb + u]; row[rb + u] = acc; acc += t;
        }
        if (sc == 63) row[IDXf(NN)] = acc;
        if (tid < 64) {
            float* drow = sm.scan[16];
            int drb = tid * 17;
            float off2 = inc2 - s2 + ((tid >= 32) ? sm.wtot[16][0] : 0.f);
            float acc2v = off2;
#pragma unroll
            for (int u = 0; u < 16; u++) {
                float t = drow[drb + u]; drow[drb + u] = acc2v; acc2v += t;
            }
            if (tid == 63) drow[IDXf(NN)] = acc2v;
        }
    }
    __syncthreads();
    {
        float wB = __expf(0.2f * msd - m);
#pragma unroll
        for (int o = 0; o < 16; o++) num[o] = wB * sm.scan[o][kthx];
        den = wB * sm.scan[16][kthx];
    }
    __syncthreads();                               // before buffer reuse

    // ======== Phase A: inclusive suffix of exp(ss_j - Mss) * hv ========
    {
        float aj = __expf(sm.key[tid] - Mss);
        const float4* hp = (const float4*)&g_hw[((size_t)b * NN + sm.idx[tid]) * DG];
        float4 h0 = hp[0], h1 = hp[1], h2 = hp[2], h3 = hp[3];
        sm.scan[0][tix]  = aj * h0.x; sm.scan[1][tix]  = aj * h0.y;
        sm.scan[2][tix]  = aj * h0.z; sm.scan[3][tix]  = aj * h0.w;
        sm.scan[4][tix]  = aj * h1.x; sm.scan[5][tix]  = aj * h1.y;
        sm.scan[6][tix]  = aj * h1.z; sm.scan[7][tix]  = aj * h1.w;
        sm.scan[8][tix]  = aj * h2.x; sm.scan[9][tix]  = aj * h2.y;
        sm.scan[10][tix] = aj * h2.z; sm.scan[11][tix] = aj * h2.w;
        sm.scan[12][tix] = aj * h3.x; sm.scan[13][tix] = aj * h3.y;
        sm.scan[14][tix] = aj * h3.z; sm.scan[15][tix] = aj * h3.w;
        sm.scan[16][tix] = aj;
    }
    __syncthreads();
    {
        float* row = sm.scan[sr];
        float s = 0.f;
#pragma unroll
        for (int u = 0; u < 16; u++) s += row[rb + u];
        float inc = s;                             // suffix scan within warp
#pragma unroll
        for (int o = 1; o < 32; o <<= 1) {
            float v = __shfl_down_sync(0xffffffffu, inc, o);
            if (lane < 32 - o) inc += v;
        }
        if (lane == 0) sm.wtot[sr][wir] = inc;

        float s2 = 0.f, inc2 = 0.f;
        if (tid < 64) {
            float* drow = sm.scan[16];
            int drb = tid * 17;
#pragma unroll
            for (int u = 0; u < 16; u++) s2 += drow[drb + u];
            inc2 = s2;
#pragma unroll
            for (int o = 1; o < 32; o <<= 1) {
                float v = __shfl_down_sync(0xffffffffu, inc2, o);
                if ((tid & 31) < 32 - o) inc2 += v;
            }
            if ((tid & 31) == 0) sm.wtot[16][tid >> 5] = inc2;
        }
        __syncthreads();

        float off = inc - s + ((wir == 0) ? sm.wtot[sr][1] : 0.f);
        float acc = off;
#pragma unroll
        for (int u = 15; u >= 0; u--) {
            acc += row[rb + u]; row[rb + u] = acc;
        }
        if (sc == 63) row[IDXf(NN)] = 0.f;
        if (tid < 64) {
            float* drow = sm.scan[16];
            int drb = tid * 17;
            float off2 = inc2 - s2 + ((tid < 32) ? sm.wtot[16][1] : 0.f);
            float acc2v = off2;
#pragma unroll
            for (int u = 15; u >= 0; u--) {
                acc2v += drow[drb + u]; drow[drb + u] = acc2v;
            }
            if (tid == 63) drow[IDXf(NN)] = 0.f;
        }
    }
    __syncthreads();
    {
        float wA = __expf(msd - m);
#pragma unroll
        for (int o = 0; o < 16; o++) num[o] += wA * sm.scan[o][kthx];
        den += wA * sm.scan[16][kthx];
    }

    // duplicated self-loop (PyG add_self_loops on dense edge list)
    {
        float e = sd + ssi;
        e = (e >= 0.f) ? e : 0.2f * e;
        float ws = __expf(e - m);
        den += ws;
        const float4* hp = (const float4*)&g_hw[((size_t)b * NN + i) * DG];
        float4 h0 = hp[0], h1 = hp[1], h2 = hp[2], h3 = hp[3];
        num[0]  += ws * h0.x; num[1]  += ws * h0.y; num[2]  += ws * h0.z; num[3]  += ws * h0.w;
        num[4]  += ws * h1.x; num[5]  += ws * h1.y; num[6]  += ws * h1.z; num[7]  += ws * h1.w;
        num[8]  += ws * h2.x; num[9]  += ws * h2.y; num[10] += ws * h2.z; num[11] += ws * h2.w;
        num[12] += ws * h3.x; num[13] += ws * h3.y; num[14] += ws * h3.z; num[15] += ws * h3.w;
    }

    const float inv = 1.f / den;
#pragma unroll
    for (int o = 0; o < 16; o++) num[o] *= inv;

    // block reduce over 1024 nodes -> pooled[16] -> fc -> out[b][2]
#pragma unroll
    for (int o = 0; o < 16; o++) {
        float v = num[o];
        v += __shfl_xor_sync(0xffffffffu, v, 16);
        v += __shfl_xor_sync(0xffffffffu, v, 8);
        v += __shfl_xor_sync(0xffffffffu, v, 4);
        v += __shfl_xor_sync(0xffffffffu, v, 2);
        v += __shfl_xor_sync(0xffffffffu, v, 1);
        if ((tid & 31) == 0) sm.wred[tid >> 5][o] = v;
    }
    __syncthreads();
    if (tid < 16) {
        float s = 0.f;
        for (int w = 0; w < 32; w++) s += sm.wred[w][tid];
        sm.pooled[tid] = s * (1.0f / (float)NN) + __ldg(&gat_b[tid]);
    }
    __syncthreads();
    if (tid < 2) {
        float r = __ldg(&fcb[tid]);
#pragma unroll
        for (int o = 0; o < 16; o++) r += sm.pooled[o] * __ldg(&fcw[tid * 16 + o]);
        out[b * 2 + tid] = r;
    }
}

extern "C" void kernel_launch(void* const* d_in, const int* in_sizes, int n_in,
                              void* d_out, int out_size) {
    const float* x    = (const float*)d_in[0];
    const float* c1w  = (const float*)d_in[1];
    const float* c1b  = (const float*)d_in[2];
    const float* c2w  = (const float*)d_in[3];
    const float* c2b  = (const float*)d_in[4];
    const float* gw   = (const float*)d_in[5];
    const float* asrc = (const float*)d_in[6];
    const float* adst = (const float*)d_in[7];
    const float* gb   = (const float*)d_in[8];
    const float* fcw  = (const float*)d_in[9];
    const float* fcb  = (const float*)d_in[10];
    float* out = (float*)d_out;

    k_conv1<<<dim3(32, BATCH), 128>>>(x, c1w, c1b);

    cudaFuncSetAttribute(k_conv2, cudaFuncAttributeMaxDynamicSharedMemorySize,
                         (int)sizeof(Conv2Sm));
    k_conv2<<<dim3(16, BATCH), 256, sizeof(Conv2Sm)>>>(c2w, c2b, gw, asrc, adst);

    cudaFuncSetAttribute(k_gat2, cudaFuncAttributeMaxDynamicSharedMemorySize,
                         (int)sizeof(GatSmem));
    k_gat2<<<BATCH, 1024, sizeof(GatSmem)>>>(gb, fcw, fcb, out);
}

// round 12
// speedup vs baseline: 1.8639x; 1.0062x over previous
#include <cuda_runtime.h>

// Problem constants
#define BATCH 128
#define CIN   17
#define TIN   4096
#define C1    32
#define T1    2048   // after pool1
#define C2    64
#define NN    1024   // nodes after pool2
#define DG    16     // GAT out dim

typedef unsigned long long ull;

// ---- packed f32x2 helpers (FFMA2 path; ptxas won't auto-fuse) ----
__device__ __forceinline__ ull pack2(float lo, float hi) {
    ull v; asm("mov.b64 %0, {%1, %2};" : "=l"(v) : "f"(lo), "f"(hi)); return v;
}
__device__ __forceinline__ void unpack2(ull v, float& lo, float& hi) {
    asm("mov.b64 {%0, %1}, %2;" : "=f"(lo), "=f"(hi) : "l"(v));
}
__device__ __forceinline__ ull ffma2(ull a, ull b, ull c) {
    ull d; asm("fma.rn.f32x2 %0, %1, %2, %3;" : "=l"(d) : "l"(a), "l"(b), "l"(c));
    return d;
}

// padded scan index: stride-17 layout kills the 16-way bank conflict
__device__ __forceinline__ int IDXf(int j) { return j + (j >> 4); }

// ---- scratch (static device allocations; no cudaMalloc anywhere) ----
__device__ float g_h1[BATCH * C1 * T1];     // 33.5 MB
__device__ float g_hw[BATCH * NN * DG];     // 8.4 MB
__device__ float g_ssrc[BATCH * NN];
__device__ float g_sdst[BATCH * NN];

// ============================================================
// conv1: x[b][17][4096] -> relu -> maxpool2 -> g_h1[b][32][2048]
// Mainloop: LDS.128 only (11 LDS + 80 FFMA2 per input channel).
// ============================================================
__global__ __launch_bounds__(128) void k_conv1(const float* __restrict__ x,
                                               const float* __restrict__ w,
                                               const float* __restrict__ bias) {
    __shared__ __align__(16) ull sdin[CIN][132];   // duplicated input, 17.9 KB
    __shared__ __align__(16) float sw[85 * 32];    // [(c*5+k)][oc] transposed
    const int b   = blockIdx.y;
    const int t0  = blockIdx.x * 128;
    const int tid = threadIdx.x;

    // weights: 2720 floats = 680 float4, scatter to transposed layout
    {
        const float4* w4 = (const float4*)w;
        for (int i = tid; i < 680; i += 128) {
            float4 v = w4[i];
            int f = i * 4;
#pragma unroll
            for (int u = 0; u < 4; u++) {
                int ff = f + u;
                int oc = ff / 85, r = ff - oc * 85;
                sw[r * 32 + oc] = (&v.x)[u];
            }
        }
    }
    // input body: 17 rows x 32 float4 (aligned, t0 multiple of 128)
    for (int i = tid; i < 17 * 32; i += 128) {
        int c = i >> 5, iv = i & 31;
        float4 v = *(const float4*)&x[(b * CIN + c) * TIN + t0 + iv * 4];
        int p = 2 + iv * 4;
        sdin[c][p]     = pack2(v.x, v.x);
        sdin[c][p + 1] = pack2(v.y, v.y);
        sdin[c][p + 2] = pack2(v.z, v.z);
        sdin[c][p + 3] = pack2(v.w, v.w);
    }
    // halo: 2 each side per row
    if (tid < 68) {
        int c = tid >> 2, u = tid & 3;
        int p = (u < 2) ? u : (128 + u);           // {0,1,130,131}
        int t = t0 - 2 + p;
        float v = (t >= 0 && t < TIN) ? x[(b * CIN + c) * TIN + t] : 0.f;
        sdin[c][p] = pack2(v, v);
    }
    __syncthreads();

    const int ocg = tid & 7, pg = tid >> 3;
    const int oc0 = ocg * 4;                       // 4 ocs = 2 packed pairs
    const int cp0 = pg * 8;                        // 8 conv positions (16B-aligned)

    ull acc2[2][8];
    {
        ull b0 = pack2(bias[oc0],     bias[oc0 + 1]);
        ull b1 = pack2(bias[oc0 + 2], bias[oc0 + 3]);
#pragma unroll
        for (int p = 0; p < 8; p++) { acc2[0][p] = b0; acc2[1][p] = b1; }
    }

    for (int c = 0; c < CIN; c++) {
        ull bb[12];
        const ulonglong2* ip = reinterpret_cast<const ulonglong2*>(&sdin[c][cp0]);
#pragma unroll
        for (int r = 0; r < 6; r++) {              // 6x LDS.128
            ulonglong2 v = ip[r];
            bb[2 * r] = v.x; bb[2 * r + 1] = v.y;
        }
#pragma unroll
        for (int k = 0; k < 5; k++) {              // 5x LDS.128 (both oc pairs)
            ulonglong2 wv = *reinterpret_cast<const ulonglong2*>(
                &sw[(c * 5 + k) * 32 + oc0]);
#pragma unroll
            for (int p = 0; p < 8; p++) {
                acc2[0][p] = ffma2(bb[p + k], wv.x, acc2[0][p]);
                acc2[1][p] = ffma2(bb[p + k], wv.y, acc2[1][p]);
            }
        }
    }

    const int pbase = blockIdx.x * 64 + pg * 4;
#pragma unroll
    for (int a2 = 0; a2 < 2; a2++)
#pragma unroll
        for (int q = 0; q < 4; q++) {
            float lo0, hi0, lo1, hi1;
            unpack2(acc2[a2][2 * q],     lo0, hi0);
            unpack2(acc2[a2][2 * q + 1], lo1, hi1);
            int oc = oc0 + 2 * a2;
            g_h1[(b * C1 + oc)     * T1 + pbase + q] = fmaxf(fmaxf(lo0, lo1), 0.f);
            g_h1[(b * C1 + oc + 1) * T1 + pbase + q] = fmaxf(fmaxf(hi0, hi1), 0.f);
        }
}

// ============================================================
// conv2 FUSED: g_h1 -> conv(32->64,k5) -> relu -> maxpool2 -> (smem)
//   -> hw = h2 @ gat_wT, s_src, s_dst
// Mainloop: LDS.128 only (14 LDS + 80 FFMA2 per input channel).
// ============================================================
struct Conv2Sm {
    union {
        ull sdin[C1][132];               // 33792 B (phase 1, duplicated)
        struct {
            float h2s[64][65];           // 16640 B (epilogue, pad 65)
            float red[2][64][4];         //  2048 B
        } ep;
    } A;
    union {
        float  sw[160 * 64];             // 40960 B ([(c*5+k)][oc], both halves)
        float4 wt4[64 * 4];              //  4096 B (epilogue: wT[d][o])
    } B;
};

extern __shared__ __align__(16) char c2raw[];

__global__ __launch_bounds__(256) void k_conv2(const float* __restrict__ w,
                                               const float* __restrict__ bias,
                                               const float* __restrict__ gw,
                                               const float* __restrict__ asrc,
                                               const float* __restrict__ adst) {
    Conv2Sm& cs = *reinterpret_cast<Conv2Sm*>(c2raw);
    const int b   = blockIdx.y;
    const int t0  = blockIdx.x * 128;
    const int tid = threadIdx.x;

    // weights: 64*160 floats = 2560 float4, scatter to [(c*5+k)*64 + oc]
    {
        const float4* w4 = (const float4*)w;
        for (int i = tid; i < 2560; i += 256) {
            float4 v = w4[i];
            int f = i * 4;
#pragma unroll
            for (int u = 0; u < 4; u++) {
                int ff = f + u;
                int oc = ff / 160, r = ff - oc * 160;
                cs.B.sw[r * 64 + oc] = (&v.x)[u];
            }
        }
    }
    // input body: 32 rows x 32 float4
    for (int i = tid; i < 32 * 32; i += 256) {
        int c = i >> 5, iv = i & 31;
        float4 v = *(const float4*)&g_h1[(b * C1 + c) * T1 + t0 + iv * 4];
        int p = 2 + iv * 4;
        cs.A.sdin[c][p]     = pack2(v.x, v.x);
        cs.A.sdin[c][p + 1] = pack2(v.y, v.y);
        cs.A.sdin[c][p + 2] = pack2(v.z, v.z);
        cs.A.sdin[c][p + 3] = pack2(v.w, v.w);
    }
    if (tid < 128) {
        int c = tid >> 2, u = tid & 3;
        int p = (u < 2) ? u : (128 + u);
        int t = t0 - 2 + p;
        float v = (t >= 0 && t < T1) ? g_h1[(b * C1 + c) * T1 + t] : 0.f;
        cs.A.sdin[c][p] = pack2(v, v);
    }
    __syncthreads();

    const int ocg = tid & 7, pg = tid >> 3;        // pg in [0,32)
    const int oc0 = ocg * 4;
    const int cp0 = pg * 4;                        // 4 conv positions (16B-aligned)

    ull acc2[2][2][4];
#pragma unroll
    for (int h = 0; h < 2; h++) {
        ull b0 = pack2(bias[h * 32 + oc0],     bias[h * 32 + oc0 + 1]);
        ull b1 = pack2(bias[h * 32 + oc0 + 2], bias[h * 32 + oc0 + 3]);
#pragma unroll
        for (int p = 0; p < 4; p++) { acc2[h][0][p] = b0; acc2[h][1][p] = b1; }
    }

    for (int c = 0; c < C1; c++) {
        ull bb[8];
        const ulonglong2* ip = reinterpret_cast<const ulonglong2*>(&cs.A.sdin[c][cp0]);
#pragma unroll
        for (int r = 0; r < 4; r++) {              // 4x LDS.128
            ulonglong2 v = ip[r];
            bb[2 * r] = v.x; bb[2 * r + 1] = v.y;
        }
#pragma unroll
        for (int k = 0; k < 5; k++) {
            const float* wb = &cs.B.sw[(c * 5 + k) * 64];
#pragma unroll
            for (int h = 0; h < 2; h++) {          // 2x LDS.128 per k
                ulonglong2 wv = *reinterpret_cast<const ulonglong2*>(
                    wb + h * 32 + oc0);
#pragma unroll
                for (int p = 0; p < 4; p++) {
                    acc2[h][0][p] = ffma2(bb[p + k], wv.x, acc2[h][0][p]);
                    acc2[h][1][p] = ffma2(bb[p + k], wv.y, acc2[h][1][p]);
                }
            }
        }
    }
    __syncthreads();                               // all sdin/sw reads done

    // pooled relu -> smem h2 tile; concurrently load wT into B union
#pragma unroll
    for (int h = 0; h < 2; h++)
#pragma unroll
        for (int a2 = 0; a2 < 2; a2++)
#pragma unroll
            for (int q = 0; q < 2; q++) {
                float lo0, hi0, lo1, hi1;
                unpack2(acc2[h][a2][2 * q],     lo0, hi0);
                unpack2(acc2[h][a2][2 * q + 1], lo1, hi1);
                int node = pg * 2 + q;
                int oc   = h * 32 + oc0 + 2 * a2;
                cs.A.ep.h2s[node][oc]     = fmaxf(fmaxf(lo0, lo1), 0.f);
                cs.A.ep.h2s[node][oc + 1] = fmaxf(fmaxf(hi0, hi1), 0.f);
            }
    {
        float* wt = (float*)cs.B.wt4;              // wt[d*16+o]
        for (int i = tid; i < 1024; i += 256) {
            int o = i >> 6, d = i & 63;
            wt[d * 16 + o] = gw[i];
        }
    }
    __syncthreads();

    // epilogue: hw[node][og*4..+3] = sum_d h2s[node][d] * wT[d][..]
    const int node = tid & 63;
    const int og   = tid >> 6;
    float acc[4] = {0.f, 0.f, 0.f, 0.f};
#pragma unroll 4
    for (int d = 0; d < 64; d++) {
        float v = cs.A.ep.h2s[node][d];
        float4 w4 = cs.B.wt4[d * 4 + og];
        acc[0] += v * w4.x; acc[1] += v * w4.y;
        acc[2] += v * w4.z; acc[3] += v * w4.w;
    }
    const int ngl = blockIdx.x * 64 + node;
    ((float4*)&g_hw[((size_t)b * NN + ngl) * DG])[og] =
        make_float4(acc[0], acc[1], acc[2], acc[3]);

    float ps = 0.f, pd = 0.f;
#pragma unroll
    for (int u = 0; u < 4; u++) {
        ps += acc[u] * __ldg(&asrc[og * 4 + u]);
        pd += acc[u] * __ldg(&adst[og * 4 + u]);
    }
    cs.A.ep.red[0][node][og] = ps;
    cs.A.ep.red[1][node][og] = pd;
    __syncthreads();
    if (tid < 64) {
        float s = cs.A.ep.red[0][tid][0] + cs.A.ep.red[0][tid][1]
                + cs.A.ep.red[0][tid][2] + cs.A.ep.red[0][tid][3];
        float d = cs.A.ep.red[1][tid][0] + cs.A.ep.red[1][tid][1]
                + cs.A.ep.red[1][tid][2] + cs.A.ep.red[1][tid][3];
        g_ssrc[b * NN + blockIdx.x * 64 + tid] = s;
        g_sdst[b * NN + blockIdx.x * 64 + tid] = d;
    }
}

// ============================================================
// Fused factorized GAT + node-mean + FC. One block per batch sample.
// Parallel chunked scans (64 threads/row) + padded smem indexing.
// ============================================================
struct GatSmem {
    float key[NN];              // sorted ss
    int   idx[NN];              // permutation
    float scan[17][1090];       // padded rows (IDXf), reused prefix/suffix
    float wtot[17][2];          // per-row warp totals for chunk combine
    float wred[32][DG];         // per-warp partial pooled sums
    float pooled[DG];
};

__global__ __launch_bounds__(1024) void k_gat2(const float* __restrict__ gat_b,
                                               const float* __restrict__ fcw,
                                               const float* __restrict__ fcb,
                                               float* __restrict__ out) {
    extern __shared__ __align__(16) char smraw[];
    GatSmem& sm = *reinterpret_cast<GatSmem*>(smraw);
    const int b   = blockIdx.x;
    const int tid = threadIdx.x;

    sm.key[tid] = g_ssrc[b * NN + tid];
    sm.idx[tid] = tid;

    // bitonic sort ascending (key, idx)
    for (int k = 2; k <= NN; k <<= 1) {
        for (int j = k >> 1; j > 0; j >>= 1) {
            __syncthreads();
            int partner = tid ^ j;
            if (partner > tid) {
                bool up = ((tid & k) == 0);
                float k0 = sm.key[tid], k1 = sm.key[partner];
                if ((k0 > k1) == up) {
                    sm.key[tid] = k1; sm.key[partner] = k0;
                    int t0 = sm.idx[tid];
                    sm.idx[tid] = sm.idx[partner];
                    sm.idx[partner] = t0;
                }
            }
        }
    }
    __syncthreads();

    const float Mss = sm.key[NN - 1];
    const int   i   = tid;
    const float sd  = g_sdst[b * NN + i];
    const float ssi = g_ssrc[b * NN + i];
    const float msd = sd + Mss;
    const float m   = (msd >= 0.f) ? msd : 0.2f * msd;

    int lo = 0, hi = NN;
    {
        const float thr = -sd;
        while (lo < hi) {
            int mid = (lo + hi) >> 1;
            if (sm.key[mid] < thr) lo = mid + 1; else hi = mid;
        }
    }
    const int kth  = lo;
    const int kthx = IDXf(kth);
    const int tix  = IDXf(tid);

    // scan-worker coordinates
    const int sr   = tid >> 6;                 // row 0..15
    const int sc   = tid & 63;                 // chunk within row
    const int lane = sc & 31;
    const int wir  = sc >> 5;                  // warp-in-row
    const int rb   = sc * 17;                  // IDXf(sc*16)

    float num[16];
    float den;

    // ======== Phase B: exclusive prefix of exp(0.2*(ss_j - Mss)) * hv ========
    {
        float bj = __expf(0.2f * (sm.key[tid] - Mss));
        const float4* hp = (const float4*)&g_hw[((size_t)b * NN + sm.idx[tid]) * DG];
        float4 h0 = hp[0], h1 = hp[1], h2 = hp[2], h3 = hp[3];
        sm.scan[0][tix]  = bj * h0.x; sm.scan[1][tix]  = bj * h0.y;
        sm.scan[2][tix]  = bj * h0.z; sm.scan[3][tix]  = bj * h0.w;
        sm.scan[4][tix]  = bj * h1.x; sm.scan[5][tix]  = bj * h1.y;
        sm.scan[6][tix]  = bj * h1.z; sm.scan[7][tix]  = bj * h1.w;
        sm.scan[8][tix]  = bj * h2.x; sm.scan[9][tix]  = bj * h2.y;
        sm.scan[10][tix] = bj * h2.z; sm.scan[11][tix] = bj * h2.w;
        sm.scan[12][tix] = bj * h3.x; sm.scan[13][tix] = bj * h3.y;
        sm.scan[14][tix] = bj * h3.z; sm.scan[15][tix] = bj * h3.w;
        sm.scan[16][tix] = bj;
    }
    __syncthreads();
    {
        // pass 1: chunk sums + warp inclusive scans
        float* row = sm.scan[sr];
        float s = 0.f;
#pragma unroll
        for (int u = 0; u < 16; u++) s += row[rb + u];
        float inc = s;
#pragma unroll
        for (int o = 1; o < 32; o <<= 1) {
            float v = __shfl_up_sync(0xffffffffu, inc, o);
            if (lane >= o) inc += v;
        }
        if (lane == 31) sm.wtot[sr][wir] = inc;

        float s2 = 0.f, inc2 = 0.f;
        if (tid < 64) {                            // den row (16), warps 0-1
            float* drow = sm.scan[16];
            int drb = tid * 17;
#pragma unroll
            for (int u = 0; u < 16; u++) s2 += drow[drb + u];
            inc2 = s2;
#pragma unroll
            for (int o = 1; o < 32; o <<= 1) {
                float v = __shfl_up_sync(0xffffffffu, inc2, o);
                if ((tid & 31) >= o) inc2 += v;
            }
            if ((tid & 31) == 31) sm.wtot[16][tid >> 5] = inc2;
        }
        __syncthreads();

        // pass 2: apply exclusive offsets
        float off = inc - s + ((wir == 1) ? sm.wtot[sr][0] : 0.f);
        float acc = off;
#pragma unroll
        for (int u = 0; u < 16; u++) {
            float t = row[rb + u]; row[rb + u] = acc; acc += t;
        }
        if (sc == 63) row[IDXf(NN)] = acc;
        if (tid < 64) {
            float* drow = sm.scan[16];
            int drb = tid * 17;
            float off2 = inc2 - s2 + ((tid >= 32) ? sm.wtot[16][0] : 0.f);
            float acc2v = off2;
#pragma unroll
            for (int u = 0; u < 16; u++) {
                float t = drow[drb + u]; drow[drb + u] = acc2v; acc2v += t;
            }
            if (tid == 63) drow[IDXf(NN)] = acc2v;
        }
    }
    __syncthreads();
    {
        float wB = __expf(0.2f * msd - m);
#pragma unroll
        for (int o = 0; o < 16; o++) num[o] = wB * sm.scan[o][kthx];
        den = wB * sm.scan[16][kthx];
    }
    __syncthreads();                               // before buffer reuse

    // ======== Phase A: inclusive suffix of exp(ss_j - Mss) * hv ========
    {
        float aj = __expf(sm.key[tid] - Mss);
        const float4* hp = (const float4*)&g_hw[((size_t)b * NN + sm.idx[tid]) * DG];
        float4 h0 = hp[0], h1 = hp[1], h2 = hp[2], h3 = hp[3];
        sm.scan[0][tix]  = aj * h0.x; sm.scan[1][tix]  = aj * h0.y;
        sm.scan[2][tix]  = aj * h0.z; sm.scan[3][tix]  = aj * h0.w;
        sm.scan[4][tix]  = aj * h1.x; sm.scan[5][tix]  = aj * h1.y;
        sm.scan[6][tix]  = aj * h1.z; sm.scan[7][tix]  = aj * h1.w;
        sm.scan[8][tix]  = aj * h2.x; sm.scan[9][tix]  = aj * h2.y;
        sm.scan[10][tix] = aj * h2.z; sm.scan[11][tix] = aj * h2.w;
        sm.scan[12][tix] = aj * h3.x; sm.scan[13][tix] = aj * h3.y;
        sm.scan[14][tix] = aj * h3.z; sm.scan[15][tix] = aj * h3.w;
        sm.scan[16][tix] = aj;
    }
    __syncthreads();
    {
        float* row = sm.scan[sr];
        float s = 0.f;
#pragma unroll
        for (int u = 0; u < 16; u++) s += row[rb + u];
        float inc = s;                             // suffix scan within warp
#pragma unroll
        for (int o = 1; o < 32; o <<= 1) {
            float v = __shfl_down_sync(0xffffffffu, inc, o);
            if (lane < 32 - o) inc += v;
        }
        if (lane == 0) sm.wtot[sr][wir] = inc;

        float s2 = 0.f, inc2 = 0.f;
        if (tid < 64) {
            float* drow = sm.scan[16];
            int drb = tid * 17;
#pragma unroll
            for (int u = 0; u < 16; u++) s2 += drow[drb + u];
            inc2 = s2;
#pragma unroll
            for (int o = 1; o < 32; o <<= 1) {
                float v = __shfl_down_sync(0xffffffffu, inc2, o);
                if ((tid & 31) < 32 - o) inc2 += v;
            }
            if ((tid & 31) == 0) sm.wtot[16][tid >> 5] = inc2;
        }
        __syncthreads();

        float off = inc - s + ((wir == 0) ? sm.wtot[sr][1] : 0.f);
        float acc = off;
#pragma unroll
        for (int u = 15; u >= 0; u--) {
            acc += row[rb + u]; row[rb + u] = acc;
        }
        if (sc == 63) row[IDXf(NN)] = 0.f;
        if (tid < 64) {
            float* drow = sm.scan[16];
            int drb = tid * 17;
            float off2 = inc2 - s2 + ((tid < 32) ? sm.wtot[16][1] : 0.f);
            float acc2v = off2;
#pragma unroll
            for (int u = 15; u >= 0; u--) {
                acc2v += drow[drb + u]; drow[drb + u] = acc2v;
            }
            if (tid == 63) drow[IDXf(NN)] = 0.f;
        }
    }
    __syncthreads();
    {
        float wA = __expf(msd - m);
#pragma unroll
        for (int o = 0; o < 16; o++) num[o] += wA * sm.scan[o][kthx];
        den += wA * sm.scan[16][kthx];
    }

    // duplicated self-loop (PyG add_self_loops on dense edge list)
    {
        float e = sd + ssi;
        e = (e >= 0.f) ? e : 0.2f * e;
        float ws = __expf(e - m);
        den += ws;
        const float4* hp = (const float4*)&g_hw[((size_t)b * NN + i) * DG];
        float4 h0 = hp[0], h1 = hp[1], h2 = hp[2], h3 = hp[3];
        num[0]  += ws * h0.x; num[1]  += ws * h0.y; num[2]  += ws * h0.z; num[3]  += ws * h0.w;
        num[4]  += ws * h1.x; num[5]  += ws * h1.y; num[6]  += ws * h1.z; num[7]  += ws * h1.w;
        num[8]  += ws * h2.x; num[9]  += ws * h2.y; num[10] += ws * h2.z; num[11] += ws * h2.w;
        num[12] += ws * h3.x; num[13] += ws * h3.y; num[14] += ws * h3.z; num[15] += ws * h3.w;
    }

    const float inv = 1.f / den;
#pragma unroll
    for (int o = 0; o < 16; o++) num[o] *= inv;

    // block reduce over 1024 nodes -> pooled[16] -> fc -> out[b][2]
#pragma unroll
    for (int o = 0; o < 16; o++) {
        float v = num[o];
        v += __shfl_xor_sync(0xffffffffu, v, 16);
        v += __shfl_xor_sync(0xffffffffu, v, 8);
        v += __shfl_xor_sync(0xffffffffu, v, 4);
        v += __shfl_xor_sync(0xffffffffu, v, 2);
        v += __shfl_xor_sync(0xffffffffu, v, 1);
        if ((tid & 31) == 0) sm.wred[tid >> 5][o] = v;
    }
    __syncthreads();
    if (tid < 16) {
        float s = 0.f;
        for (int w = 0; w < 32; w++) s += sm.wred[w][tid];
        sm.pooled[tid] = s * (1.0f / (float)NN) + __ldg(&gat_b[tid]);
    }
    __syncthreads();
    if (tid < 2) {
        float r = __ldg(&fcb[tid]);
#pragma unroll
        for (int o = 0; o < 16; o++) r += sm.pooled[o] * __ldg(&fcw[tid * 16 + o]);
        out[b * 2 + tid] = r;
    }
}

extern "C" void kernel_launch(void* const* d_in, const int* in_sizes, int n_in,
                              void* d_out, int out_size) {
    const float* x    = (const float*)d_in[0];
    const float* c1w  = (const float*)d_in[1];
    const float* c1b  = (const float*)d_in[2];
    const float* c2w  = (const float*)d_in[3];
    const float* c2b  = (const float*)d_in[4];
    const float* gw   = (const float*)d_in[5];
    const float* asrc = (const float*)d_in[6];
    const float* adst = (const float*)d_in[7];
    const float* gb   = (const float*)d_in[8];
    const float* fcw  = (const float*)d_in[9];
    const float* fcb  = (const float*)d_in[10];
    float* out = (float*)d_out;

    k_conv1<<<dim3(32, BATCH), 128>>>(x, c1w, c1b);

    cudaFuncSetAttribute(k_conv2, cudaFuncAttributeMaxDynamicSharedMemorySize,
                         (int)sizeof(Conv2Sm));
    k_conv2<<<dim3(16, BATCH), 256, sizeof(Conv2Sm)>>>(c2w, c2b, gw, asrc, adst);

    cudaFuncSetAttribute(k_gat2, cudaFuncAttributeMaxDynamicSharedMemorySize,
                         (int)sizeof(GatSmem));
    k_gat2<<<BATCH, 1024, sizeof(GatSmem)>>>(gb, fcw, fcb, out);
}

// round 13
// speedup vs baseline: 2.1868x; 1.1733x over previous
#include <cuda_runtime.h>

// Problem constants
#define BATCH 128
#define CIN   17
#define TIN   4096
#define C1    32
#define T1    2048   // after pool1
#define C2    64
#define NN    1024   // nodes after pool2
#define DG    16     // GAT out dim

typedef unsigned long long ull;

// ---- packed f32x2 helpers (FFMA2 path; ptxas won't auto-fuse) ----
__device__ __forceinline__ ull pack2(float lo, float hi) {
    ull v; asm("mov.b64 %0, {%1, %2};" : "=l"(v) : "f"(lo), "f"(hi)); return v;
}
__device__ __forceinline__ void unpack2(ull v, float& lo, float& hi) {
    asm("mov.b64 {%0, %1}, %2;" : "=f"(lo), "=f"(hi) : "l"(v));
}
__device__ __forceinline__ ull ffma2(ull a, ull b, ull c) {
    ull d; asm("fma.rn.f32x2 %0, %1, %2, %3;" : "=l"(d) : "l"(a), "l"(b), "l"(c));
    return d;
}

// padded scan index: stride-17 layout kills the 16-way bank conflict
__device__ __forceinline__ int IDXf(int j) { return j + (j >> 4); }

// ---- scratch (static device allocations; no cudaMalloc anywhere) ----
__device__ float g_h1[BATCH * C1 * T1];     // 33.5 MB
__device__ float g_hw[BATCH * NN * DG];     // 8.4 MB
__device__ float g_ssrc[BATCH * NN];
__device__ float g_sdst[BATCH * NN];

// ============================================================
// conv1: x[b][17][4096] -> relu -> maxpool2 -> g_h1[b][32][2048]
// Raw (un-duplicated) inputs in smem: 48B in + 80B w per thread-channel.
// Dup pairs rebuilt in registers (alu pipe has headroom).
// ============================================================
__global__ __launch_bounds__(128) void k_conv1(const float* __restrict__ x,
                                               const float* __restrict__ w,
                                               const float* __restrict__ bias) {
    __shared__ __align__(16) float sinp[CIN][132];  // raw input, 9 KB
    __shared__ __align__(16) float sw[85 * 32];     // [(c*5+k)][oc] transposed
    const int b   = blockIdx.y;
    const int t0  = blockIdx.x * 128;
    const int tid = threadIdx.x;

    // weights: 2720 floats = 680 float4, scatter to transposed layout
    {
        const float4* w4 = (const float4*)w;
        for (int i = tid; i < 680; i += 128) {
            float4 v = w4[i];
            int f = i * 4;
#pragma unroll
            for (int u = 0; u < 4; u++) {
                int ff = f + u;
                int oc = ff / 85, r = ff - oc * 85;
                sw[r * 32 + oc] = (&v.x)[u];
            }
        }
    }
    // input body: 17 rows x 32 float4 (aligned global reads, scalar smem writes)
    for (int i = tid; i < 17 * 32; i += 128) {
        int c = i >> 5, iv = i & 31;
        float4 v = *(const float4*)&x[(b * CIN + c) * TIN + t0 + iv * 4];
        int p = 2 + iv * 4;
        sinp[c][p]     = v.x;
        sinp[c][p + 1] = v.y;
        sinp[c][p + 2] = v.z;
        sinp[c][p + 3] = v.w;
    }
    // halo: 2 each side per row
    if (tid < 68) {
        int c = tid >> 2, u = tid & 3;
        int p = (u < 2) ? u : (128 + u);           // {0,1,130,131}
        int t = t0 - 2 + p;
        sinp[c][p] = (t >= 0 && t < TIN) ? x[(b * CIN + c) * TIN + t] : 0.f;
    }
    __syncthreads();

    const int ocg = tid & 7, pg = tid >> 3;
    const int oc0 = ocg * 4;                       // 4 ocs = 2 packed pairs
    const int cp0 = pg * 8;                        // 8 conv positions (16B-aligned)

    ull acc2[2][8];
    {
        ull b0 = pack2(bias[oc0],     bias[oc0 + 1]);
        ull b1 = pack2(bias[oc0 + 2], bias[oc0 + 3]);
#pragma unroll
        for (int p = 0; p < 8; p++) { acc2[0][p] = b0; acc2[1][p] = b1; }
    }

    for (int c = 0; c < CIN; c++) {
        const float4* ip = (const float4*)&sinp[c][cp0];
        float4 v0 = ip[0], v1 = ip[1], v2 = ip[2];  // 3x LDS.128 = 48B
        ull bb[12];
        bb[0]  = pack2(v0.x, v0.x); bb[1]  = pack2(v0.y, v0.y);
        bb[2]  = pack2(v0.z, v0.z); bb[3]  = pack2(v0.w, v0.w);
        bb[4]  = pack2(v1.x, v1.x); bb[5]  = pack2(v1.y, v1.y);
        bb[6]  = pack2(v1.z, v1.z); bb[7]  = pack2(v1.w, v1.w);
        bb[8]  = pack2(v2.x, v2.x); bb[9]  = pack2(v2.y, v2.y);
        bb[10] = pack2(v2.z, v2.z); bb[11] = pack2(v2.w, v2.w);
#pragma unroll
        for (int k = 0; k < 5; k++) {              // 5x LDS.128 = 80B
            ulonglong2 wv = *reinterpret_cast<const ulonglong2*>(
                &sw[(c * 5 + k) * 32 + oc0]);
#pragma unroll
            for (int p = 0; p < 8; p++) {
                acc2[0][p] = ffma2(bb[p + k], wv.x, acc2[0][p]);
                acc2[1][p] = ffma2(bb[p + k], wv.y, acc2[1][p]);
            }
        }
    }

    const int pbase = blockIdx.x * 64 + pg * 4;
#pragma unroll
    for (int a2 = 0; a2 < 2; a2++)
#pragma unroll
        for (int q = 0; q < 4; q++) {
            float lo0, hi0, lo1, hi1;
            unpack2(acc2[a2][2 * q],     lo0, hi0);
            unpack2(acc2[a2][2 * q + 1], lo1, hi1);
            int oc = oc0 + 2 * a2;
            g_h1[(b * C1 + oc)     * T1 + pbase + q] = fmaxf(fmaxf(lo0, lo1), 0.f);
            g_h1[(b * C1 + oc + 1) * T1 + pbase + q] = fmaxf(fmaxf(hi0, hi1), 0.f);
        }
}

// ============================================================
// conv2 FUSED: g_h1 -> conv(32->64,k5) -> relu -> maxpool2 -> (smem)
//   -> hw = h2 @ gat_wT, s_src, s_dst
// Remapped: 16 ocg x 16 pg (4 ocs x 8 positions per thread) so weight
// bytes amortize over 2x positions: 128B total per thread-channel.
// ============================================================
struct Conv2Sm {
    union {
        float sinp[C1][132];             // 16896 B (phase 1, raw)
        float h2s[64][65];               // 16640 B (epilogue, pad 65)
    } A;
    union {
        float sw[160 * 64];              // 40960 B ([(c*5+k)][oc], all 64 ocs)
        struct {
            float4 wt4[64 * 4];          //  4096 B (epilogue: wT[d][o])
            float  red[2][64][4];        //  2048 B
        } ep;
    } B;
};

extern __shared__ __align__(16) char c2raw[];

__global__ __launch_bounds__(256) void k_conv2(const float* __restrict__ w,
                                               const float* __restrict__ bias,
                                               const float* __restrict__ gw,
                                               const float* __restrict__ asrc,
                                               const float* __restrict__ adst) {
    Conv2Sm& cs = *reinterpret_cast<Conv2Sm*>(c2raw);
    const int b   = blockIdx.y;
    const int t0  = blockIdx.x * 128;
    const int tid = threadIdx.x;

    // weights: 64*160 floats = 2560 float4, scatter to [(c*5+k)*64 + oc]
    {
        const float4* w4 = (const float4*)w;
        for (int i = tid; i < 2560; i += 256) {
            float4 v = w4[i];
            int f = i * 4;
#pragma unroll
            for (int u = 0; u < 4; u++) {
                int ff = f + u;
                int oc = ff / 160, r = ff - oc * 160;
                cs.B.sw[r * 64 + oc] = (&v.x)[u];
            }
        }
    }
    // input body: 32 rows x 32 float4
    for (int i = tid; i < 32 * 32; i += 256) {
        int c = i >> 5, iv = i & 31;
        float4 v = *(const float4*)&g_h1[(b * C1 + c) * T1 + t0 + iv * 4];
        int p = 2 + iv * 4;
        cs.A.sinp[c][p]     = v.x;
        cs.A.sinp[c][p + 1] = v.y;
        cs.A.sinp[c][p + 2] = v.z;
        cs.A.sinp[c][p + 3] = v.w;
    }
    if (tid < 128) {
        int c = tid >> 2, u = tid & 3;
        int p = (u < 2) ? u : (128 + u);
        int t = t0 - 2 + p;
        cs.A.sinp[c][p] = (t >= 0 && t < T1) ? g_h1[(b * C1 + c) * T1 + t] : 0.f;
    }
    __syncthreads();

    const int ocg = tid & 15, pg = tid >> 4;       // 16 oc-groups x 16 pos-groups
    const int oc0 = ocg * 4;                       // covers all 64 ocs
    const int cp0 = pg * 8;                        // 8 conv positions

    ull acc2[2][8];
    {
        ull b0 = pack2(bias[oc0],     bias[oc0 + 1]);
        ull b1 = pack2(bias[oc0 + 2], bias[oc0 + 3]);
#pragma unroll
        for (int p = 0; p < 8; p++) { acc2[0][p] = b0; acc2[1][p] = b1; }
    }

    for (int c = 0; c < C1; c++) {
        const float4* ip = (const float4*)&cs.A.sinp[c][cp0];
        float4 v0 = ip[0], v1 = ip[1], v2 = ip[2];  // 48B
        ull bb[12];
        bb[0]  = pack2(v0.x, v0.x); bb[1]  = pack2(v0.y, v0.y);
        bb[2]  = pack2(v0.z, v0.z); bb[3]  = pack2(v0.w, v0.w);
        bb[4]  = pack2(v1.x, v1.x); bb[5]  = pack2(v1.y, v1.y);
        bb[6]  = pack2(v1.z, v1.z); bb[7]  = pack2(v1.w, v1.w);
        bb[8]  = pack2(v2.x, v2.x); bb[9]  = pack2(v2.y, v2.y);
        bb[10] = pack2(v2.z, v2.z); bb[11] = pack2(v2.w, v2.w);
#pragma unroll
        for (int k = 0; k < 5; k++) {              // 80B weights
            ulonglong2 wv = *reinterpret_cast<const ulonglong2*>(
                &cs.B.sw[(c * 5 + k) * 64 + oc0]);
#pragma unroll
            for (int p = 0; p < 8; p++) {
                acc2[0][p] = ffma2(bb[p + k], wv.x, acc2[0][p]);
                acc2[1][p] = ffma2(bb[p + k], wv.y, acc2[1][p]);
            }
        }
    }
    __syncthreads();                               // all sinp/sw reads done

    // pooled relu -> smem h2 tile; concurrently load wT into B union
#pragma unroll
    for (int a2 = 0; a2 < 2; a2++)
#pragma unroll
        for (int q = 0; q < 4; q++) {
            float lo0, hi0, lo1, hi1;
            unpack2(acc2[a2][2 * q],     lo0, hi0);
            unpack2(acc2[a2][2 * q + 1], lo1, hi1);
            int node = pg * 4 + q;
            int oc   = oc0 + 2 * a2;
            cs.A.h2s[node][oc]     = fmaxf(fmaxf(lo0, lo1), 0.f);
            cs.A.h2s[node][oc + 1] = fmaxf(fmaxf(hi0, hi1), 0.f);
        }
    {
        float* wt = (float*)cs.B.ep.wt4;           // wt[d*16+o]
        for (int i = tid; i < 1024; i += 256) {
            int o = i >> 6, d = i & 63;
            wt[d * 16 + o] = gw[i];
        }
    }
    __syncthreads();

    // epilogue: hw[node][og*4..+3] = sum_d h2s[node][d] * wT[d][..]
    const int node = tid & 63;
    const int og   = tid >> 6;
    float acc[4] = {0.f, 0.f, 0.f, 0.f};
#pragma unroll 4
    for (int d = 0; d < 64; d++) {
        float v = cs.A.h2s[node][d];
        float4 w4 = cs.B.ep.wt4[d * 4 + og];
        acc[0] += v * w4.x; acc[1] += v * w4.y;
        acc[2] += v * w4.z; acc[3] += v * w4.w;
    }
    const int ngl = blockIdx.x * 64 + node;
    ((float4*)&g_hw[((size_t)b * NN + ngl) * DG])[og] =
        make_float4(acc[0], acc[1], acc[2], acc[3]);

    float ps = 0.f, pd = 0.f;
#pragma unroll
    for (int u = 0; u < 4; u++) {
        ps += acc[u] * __ldg(&asrc[og * 4 + u]);
        pd += acc[u] * __ldg(&adst[og * 4 + u]);
    }
    cs.B.ep.red[0][node][og] = ps;
    cs.B.ep.red[1][node][og] = pd;
    __syncthreads();
    if (tid < 64) {
        float s = cs.B.ep.red[0][tid][0] + cs.B.ep.red[0][tid][1]
                + cs.B.ep.red[0][tid][2] + cs.B.ep.red[0][tid][3];
        float d = cs.B.ep.red[1][tid][0] + cs.B.ep.red[1][tid][1]
                + cs.B.ep.red[1][tid][2] + cs.B.ep.red[1][tid][3];
        g_ssrc[b * NN + blockIdx.x * 64 + tid] = s;
        g_sdst[b * NN + blockIdx.x * 64 + tid] = d;
    }
}

// ============================================================
// Fused factorized GAT + node-mean + FC. One block per batch sample.
// (unchanged from R11)
// ============================================================
struct GatSmem {
    float key[NN];              // sorted ss
    int   idx[NN];              // permutation
    float scan[17][1090];       // padded rows (IDXf), reused prefix/suffix
    float wtot[17][2];          // per-row warp totals for chunk combine
    float wred[32][DG];         // per-warp partial pooled sums
    float pooled[DG];
};

__global__ __launch_bounds__(1024) void k_gat2(const float* __restrict__ gat_b,
                                               const float* __restrict__ fcw,
                                               const float* __restrict__ fcb,
                                               float* __restrict__ out) {
    extern __shared__ __align__(16) char smraw[];
    GatSmem& sm = *reinterpret_cast<GatSmem*>(smraw);
    const int b   = blockIdx.x;
    const int tid = threadIdx.x;

    sm.key[tid] = g_ssrc[b * NN + tid];
    sm.idx[tid] = tid;

    // bitonic sort ascending (key, idx)
    for (int k = 2; k <= NN; k <<= 1) {
        for (int j = k >> 1; j > 0; j >>= 1) {
            __syncthreads();
            int partner = tid ^ j;
            if (partner > tid) {
                bool up = ((tid & k) == 0);
                float k0 = sm.key[tid], k1 = sm.key[partner];
                if ((k0 > k1) == up) {
                    sm.key[tid] = k1; sm.key[partner] = k0;
                    int t0 = sm.idx[tid];
                    sm.idx[tid] = sm.idx[partner];
                    sm.idx[partner] = t0;
                }
            }
        }
    }
    __syncthreads();

    const float Mss = sm.key[NN - 1];
    const int   i   = tid;
    const float sd  = g_sdst[b * NN + i];
    const float ssi = g_ssrc[b * NN + i];
    const float msd = sd + Mss;
    const float m   = (msd >= 0.f) ? msd : 0.2f * msd;

    int lo = 0, hi = NN;
    {
        const float thr = -sd;
        while (lo < hi) {
            int mid = (lo + hi) >> 1;
            if (sm.key[mid] < thr) lo = mid + 1; else hi = mid;
        }
    }
    const int kth  = lo;
    const int kthx = IDXf(kth);
    const int tix  = IDXf(tid);

    // scan-worker coordinates
    const int sr   = tid >> 6;                 // row 0..15
    const int sc   = tid & 63;                 // chunk within row
    const int lane = sc & 31;
    const int wir  = sc >> 5;                  // warp-in-row
    const int rb   = sc * 17;                  // IDXf(sc*16)

    float num[16];
    float den;

    // ======== Phase B: exclusive prefix of exp(0.2*(ss_j - Mss)) * hv ========
    {
        float bj = __expf(0.2f * (sm.key[tid] - Mss));
        const float4* hp = (const float4*)&g_hw[((size_t)b * NN + sm.idx[tid]) * DG];
        float4 h0 = hp[0], h1 = hp[1], h2 = hp[2], h3 = hp[3];
        sm.scan[0][tix]  = bj * h0.x; sm.scan[1][tix]  = bj * h0.y;
        sm.scan[2][tix]  = bj * h0.z; sm.scan[3][tix]  = bj * h0.w;
        sm.scan[4][tix]  = bj * h1.x; sm.scan[5][tix]  = bj * h1.y;
        sm.scan[6][tix]  = bj * h1.z; sm.scan[7][tix]  = bj * h1.w;
        sm.scan[8][tix]  = bj * h2.x; sm.scan[9][tix]  = bj * h2.y;
        sm.scan[10][tix] = bj * h2.z; sm.scan[11][tix] = bj * h2.w;
        sm.scan[12][tix] = bj * h3.x; sm.scan[13][tix] = bj * h3.y;
        sm.scan[14][tix] = bj * h3.z; sm.scan[15][tix] = bj * h3.w;
        sm.scan[16][tix] = bj;
    }
    __syncthreads();
    {
        // pass 1: chunk sums + warp inclusive scans
        float* row = sm.scan[sr];
        float s = 0.f;
#pragma unroll
        for (int u = 0; u < 16; u++) s += row[rb + u];
        float inc = s;
#pragma unroll
        for (int o = 1; o < 32; o <<= 1) {
            float v = __shfl_up_sync(0xffffffffu, inc, o);
            if (lane >= o) inc += v;
        }
        if (lane == 31) sm.wtot[sr][wir] = inc;

        float s2 = 0.f, inc2 = 0.f;
        if (tid < 64) {                            // den row (16), warps 0-1
            float* drow = sm.scan[16];
            int drb = tid * 17;
#pragma unroll
            for (int u = 0; u < 16; u++) s2 += drow[drb + u];
            inc2 = s2;
#pragma unroll
            for (int o = 1; o < 32; o <<= 1) {
                float v = __shfl_up_sync(0xffffffffu, inc2, o);
                if ((tid & 31) >= o) inc2 += v;
            }
            if ((tid & 31) == 31) sm.wtot[16][tid >> 5] = inc2;
        }
        __syncthreads();

        // pass 2: apply exclusive offsets
        float off = inc - s + ((wir == 1) ? sm.wtot[sr][0] : 0.f);
        float acc = off;
#pragma unroll
        for (int u = 0; u < 16; u++) {
            float t = row[rb + u]; row[rb + u] = acc; acc += t;
        }
        if (sc == 63) row[IDXf(NN)] = acc;
        if (tid < 64) {
            float* drow = sm.scan[16];
            int drb = tid * 17;
            float off2 = inc2 - s2 + ((tid >= 32) ? sm.wtot[16][0] : 0.f);
            float acc2v = off2;
#pragma unroll
            for (int u = 0; u < 16; u++) {
                float t = drow[drb + u]; drow[drb + u] = acc2v; acc2v += t;
            }
            if (tid == 63) drow[IDXf(NN)] = acc2v;
        }
    }
    __syncthreads();
    {
        float wB = __expf(0.2f * msd - m);
#pragma unroll
        for (int o = 0; o < 16; o++) num[o] = wB * sm.scan[o][kthx];
        den = wB * sm.scan[16][kthx];
    }
    __syncthreads();                               // before buffer reuse

    // ======== Phase A: inclusive suffix of exp(ss_j - Mss) * hv ========
    {
        float aj = __expf(sm.key[tid] - Mss);
        const float4* hp = (const float4*)&g_hw[((size_t)b * NN + sm.idx[tid]) * DG];
        float4 h0 = hp[0], h1 = hp[1], h2 = hp[2], h3 = hp[3];
        sm.scan[0][tix]  = aj * h0.x; sm.scan[1][tix]  = aj * h0.y;
        sm.scan[2][tix]  = aj * h0.z; sm.scan[3][tix]  = aj * h0.w;
        sm.scan[4][tix]  = aj * h1.x; sm.scan[5][tix]  = aj * h1.y;
        sm.scan[6][tix]  = aj * h1.z; sm.scan[7][tix]  = aj * h1.w;
        sm.scan[8][tix]  = aj * h2.x; sm.scan[9][tix]  = aj * h2.y;
        sm.scan[10][tix] = aj * h2.z; sm.scan[11][tix] = aj * h2.w;
        sm.scan[12][tix] = aj * h3.x; sm.scan[13][tix] = aj * h3.y;
        sm.scan[14][tix] = aj * h3.z; sm.scan[15][tix] = aj * h3.w;
        sm.scan[16][tix] = aj;
    }
    __syncthreads();
    {
        float* row = sm.scan[sr];
        float s = 0.f;
#pragma unroll
        for (int u = 0; u < 16; u++) s += row[rb + u];
        float inc = s;                             // suffix scan within warp
#pragma unroll
        for (int o = 1; o < 32; o <<= 1) {
            float v = __shfl_down_sync(0xffffffffu, inc, o);
            if (lane < 32 - o) inc += v;
        }
        if (lane == 0) sm.wtot[sr][wir] = inc;

        float s2 = 0.f, inc2 = 0.f;
        if (tid < 64) {
            float* drow = sm.scan[16];
            int drb = tid * 17;
#pragma unroll
            for (int u = 0; u < 16; u++) s2 += drow[drb + u];
            inc2 = s2;
#pragma unroll
            for (int o = 1; o < 32; o <<= 1) {
                float v = __shfl_down_sync(0xffffffffu, inc2, o);
                if ((tid & 31) < 32 - o) inc2 += v;
            }
            if ((tid & 31) == 0) sm.wtot[16][tid >> 5] = inc2;
        }
        __syncthreads();

        float off = inc - s + ((wir == 0) ? sm.wtot[sr][1] : 0.f);
        float acc = off;
#pragma unroll
        for (int u = 15; u >= 0; u--) {
            acc += row[rb + u]; row[rb + u] = acc;
        }
        if (sc == 63) row[IDXf(NN)] = 0.f;
        if (tid < 64) {
            float* drow = sm.scan[16];
            int drb = tid * 17;
            float off2 = inc2 - s2 + ((tid < 32) ? sm.wtot[16][1] : 0.f);
            float acc2v = off2;
#pragma unroll
            for (int u = 15; u >= 0; u--) {
                acc2v += drow[drb + u]; drow[drb + u] = acc2v;
            }
            if (tid == 63) drow[IDXf(NN)] = 0.f;
        }
    }
    __syncthreads();
    {
        float wA = __expf(msd - m);
#pragma unroll
        for (int o = 0; o < 16; o++) num[o] += wA * sm.scan[o][kthx];
        den += wA * sm.scan[16][kthx];
    }

    // duplicated self-loop (PyG add_self_loops on dense edge list)
    {
        float e = sd + ssi;
        e = (e >= 0.f) ? e : 0.2f * e;
        float ws = __expf(e - m);
        den += ws;
        const float4* hp = (const float4*)&g_hw[((size_t)b * NN + i) * DG];
        float4 h0 = hp[0], h1 = hp[1], h2 = hp[2], h3 = hp[3];
        num[0]  += ws * h0.x; num[1]  += ws * h0.y; num[2]  += ws * h0.z; num[3]  += ws * h0.w;
        num[4]  += ws * h1.x; num[5]  += ws * h1.y; num[6]  += ws * h1.z; num[7]  += ws * h1.w;
        num[8]  += ws * h2.x; num[9]  += ws * h2.y; num[10] += ws * h2.z; num[11] += ws * h2.w;
        num[12] += ws * h3.x; num[13] += ws * h3.y; num[14] += ws * h3.z; num[15] += ws * h3.w;
    }

    const float inv = 1.f / den;
#pragma unroll
    for (int o = 0; o < 16; o++) num[o] *= inv;

    // block reduce over 1024 nodes -> pooled[16] -> fc -> out[b][2]
#pragma unroll
    for (int o = 0; o < 16; o++) {
        float v = num[o];
        v += __shfl_xor_sync(0xffffffffu, v, 16);
        v += __shfl_xor_sync(0xffffffffu, v, 8);
        v += __shfl_xor_sync(0xffffffffu, v, 4);
        v += __shfl_xor_sync(0xffffffffu, v, 2);
        v += __shfl_xor_sync(0xffffffffu, v, 1);
        if ((tid & 31) == 0) sm.wred[tid >> 5][o] = v;
    }
    __syncthreads();
    if (tid < 16) {
        float s = 0.f;
        for (int w = 0; w < 32; w++) s += sm.wred[w][tid];
        sm.pooled[tid] = s * (1.0f / (float)NN) + __ldg(&gat_b[tid]);
    }
    __syncthreads();
    if (tid < 2) {
        float r = __ldg(&fcb[tid]);
#pragma unroll
        for (int o = 0; o < 16; o++) r += sm.pooled[o] * __ldg(&fcw[tid * 16 + o]);
        out[b * 2 + tid] = r;
    }
}

extern "C" void kernel_launch(void* const* d_in, const int* in_sizes, int n_in,
                              void* d_out, int out_size) {
    const float* x    = (const float*)d_in[0];
    const float* c1w  = (const float*)d_in[1];
    const float* c1b  = (const float*)d_in[2];
    const float* c2w  = (const float*)d_in[3];
    const float* c2b  = (const float*)d_in[4];
    const float* gw   = (const float*)d_in[5];
    const float* asrc = (const float*)d_in[6];
    const float* adst = (const float*)d_in[7];
    const float* gb   = (const float*)d_in[8];
    const float* fcw  = (const float*)d_in[9];
    const float* fcb  = (const float*)d_in[10];
    float* out = (float*)d_out;

    k_conv1<<<dim3(32, BATCH), 128>>>(x, c1w, c1b);

    cudaFuncSetAttribute(k_conv2, cudaFuncAttributeMaxDynamicSharedMemorySize,
                         (int)sizeof(Conv2Sm));
    k_conv2<<<dim3(16, BATCH), 256, sizeof(Conv2Sm)>>>(c2w, c2b, gw, asrc, adst);

    cudaFuncSetAttribute(k_gat2, cudaFuncAttributeMaxDynamicSharedMemorySize,
                         (int)sizeof(GatSmem));
    k_gat2<<<BATCH, 1024, sizeof(GatSmem)>>>(gb, fcw, fcb, out);
}